// round 13
// baseline (speedup 1.0000x reference)
#include <cuda_runtime.h>
#include <cuda_fp16.h>
#include <math.h>
#include <stdint.h>

// ---------------------------------------------------------------------------
// Problem constants: B=4, N=4096, H=1024, HEADS=16, DH=64, PSI=64, M=B*N=16384
// ---------------------------------------------------------------------------
#define Bq    4
#define SEQ   4096
#define HID   1024
#define NHEAD 16
#define DH    64
#define PSI   64
#define MROWS (Bq * SEQ)
#define EPSV  1e-5f

// Weight offsets in the packed split-weight buffers (element counts)
#define OFF_QKV  0
#define OFF_WOUT 3145728
#define OFF_W1   4194304
#define OFF_W2   8388608
#define OFF_W3   12582912
#define OFF_W4   16777216
#define WTOT     20971520

// ---------------------------------------------------------------------------
// Static device scratch
// ---------------------------------------------------------------------------
__device__ float  g_qkv [MROWS * 3 * HID];
__device__ float  g_kn  [MROWS * HID];
__device__ float  g_vn  [MROWS * HID];
__device__ float  g_dots[Bq * NHEAD * DH * DH];
__device__ float  g_x1  [MROWS * HID];
__device__ float  g_xp  [MROWS * PSI];
__device__ float  g_xn  [MROWS * PSI];
__device__ float  g_xs  [MROWS * PSI];
__device__ float  g_stats[2 * PSI];
__device__ float  g_kern[Bq * PSI * HID];
__device__ float  g_fx1 [MROWS * HID];
// split-fp16 operand buffers
__device__ __half g_wh  [WTOT];
__device__ __half g_wl  [WTOT];
__device__ __half g_lnh [MROWS * HID];
__device__ __half g_lnl [MROWS * HID];
__device__ __half g_atth[MROWS * HID];
__device__ __half g_attl[MROWS * HID];
__device__ __half g_midh[MROWS * 4 * HID];
__device__ __half g_midl[MROWS * 4 * HID];

// ---------------------------------------------------------------------------
// PTX helpers
// ---------------------------------------------------------------------------
__device__ __forceinline__ void cp_async16(uint32_t dst, const void* src) {
    asm volatile("cp.async.cg.shared.global [%0], [%1], 16;"
                 :: "r"(dst), "l"(src));
}
#define CP_COMMIT()  asm volatile("cp.async.commit_group;")
#define CP_WAIT(n)   asm volatile("cp.async.wait_group %0;" :: "n"(n))

__device__ __forceinline__ void ldm_x4(uint32_t* r, uint32_t addr) {
    asm volatile("ldmatrix.sync.aligned.m8n8.x4.shared.b16 {%0,%1,%2,%3}, [%4];"
                 : "=r"(r[0]), "=r"(r[1]), "=r"(r[2]), "=r"(r[3]) : "r"(addr));
}
__device__ __forceinline__ void ldm_x4_t(uint32_t* r, uint32_t addr) {
    asm volatile("ldmatrix.sync.aligned.m8n8.x4.trans.shared.b16 {%0,%1,%2,%3}, [%4];"
                 : "=r"(r[0]), "=r"(r[1]), "=r"(r[2]), "=r"(r[3]) : "r"(addr));
}
// fp32-accumulator HMMA (main term)
#define MMA_F16(c0,c1,c2,c3,a0,a1,a2,a3,b0,b1)                              \
    asm volatile("mma.sync.aligned.m16n8k16.row.col.f32.f16.f16.f32 "       \
                 "{%0,%1,%2,%3}, {%4,%5,%6,%7}, {%8,%9}, {%0,%1,%2,%3};"    \
                 : "+f"(c0), "+f"(c1), "+f"(c2), "+f"(c3)                   \
                 : "r"(a0), "r"(a1), "r"(a2), "r"(a3), "r"(b0), "r"(b1))
// fp16-accumulator HMMA (cross terms; 2 packed f16x2 output regs)
#define MMA_F16H(c0,c1,a0,a1,a2,a3,b0,b1)                                   \
    asm volatile("mma.sync.aligned.m16n8k16.row.col.f16.f16.f16.f16 "       \
                 "{%0,%1}, {%2,%3,%4,%5}, {%6,%7}, {%0,%1};"                \
                 : "+r"(c0), "+r"(c1)                                       \
                 : "r"(a0), "r"(a1), "r"(a2), "r"(a3), "r"(b0), "r"(b1))

// fp16 Dekker split: v ~= hi + lo (pair carries ~22 mantissa bits)
__device__ __forceinline__ void h_split(float v, __half& hi, __half& lo) {
    const __half h = __float2half_rn(v);
    hi = h;
    lo = __float2half_rn(v - __half2float(h));
}

// ---------------------------------------------------------------------------
// Split-fp16 GEMM: C = (Ah+Al) @ (Bh+Bl) (+bias)(+gelu)(+res).
// Main term Ah*Bh in fp32-accum HMMA; cross terms Al*Bh + Ah*Bl in
// fp16-accum HMMA (2x rate on most parts), folded into fp32 at epilogue.
// Tile 128x128x32, 256 threads (2x4 warps, warp 64x32), 2-stage cp.async,
// 2 CTAs/SM. M%128==0, N%128==0, K%32==0.
// ---------------------------------------------------------------------------
#define ASTR 40                          // halves per A row (32 + 8 pad)
#define BSTR 136                         // halves per B row (128 + 8 pad)
#define A_SZ (128 * ASTR)                // 5120 halves
#define B_SZ (32 * BSTR)                 // 4352 halves
#define STG  (2 * A_SZ + 2 * B_SZ)       // 18944 halves per stage
#define H16_SMEM_BYTES (2 * STG * 2)     // 75776 bytes -> 2 CTAs/SM

template <bool BIAS, bool RES, bool GELU, bool SPLITOUT>
__global__ void __launch_bounds__(256, 2) h16_gemm_kernel(
    const __half* __restrict__ Ah, const __half* __restrict__ Al,
    const __half* __restrict__ Bh, const __half* __restrict__ Bl,
    float* __restrict__ C, __half* __restrict__ Ch, __half* __restrict__ Cl,
    const float* __restrict__ bias, const float* __restrict__ res,
    int M, int K, int N)
{
    extern __shared__ __half hsm[];
    const uint32_t smb = (uint32_t)__cvta_generic_to_shared(hsm);

    const int tid  = threadIdx.x;
    const int w    = tid >> 5;
    const int lane = tid & 31;
    const int grp  = lane >> 2;
    const int qd   = lane & 3;
    const int wm   = w >> 2;             // 0..1
    const int wn   = w & 3;              // 0..3
    const int mb   = wm * 64;
    const int nb   = wn * 32;

    const int bm = blockIdx.y * 128;
    const int bn = blockIdx.x * 128;

    float acc[4][4][4];
    uint32_t acc16[4][4][2];
#pragma unroll
    for (int mi = 0; mi < 4; mi++)
#pragma unroll
        for (int ni = 0; ni < 4; ni++) {
#pragma unroll
            for (int r = 0; r < 4; r++) acc[mi][ni][r] = 0.f;
            acc16[mi][ni][0] = 0u;
            acc16[mi][ni][1] = 0u;
        }

    const int chunks = K >> 5;

    auto load_stage = [&](int c, int s) {
        const int k0 = c << 5;
        const uint32_t sb = smb + (uint32_t)(s * STG * 2);
        // A: 512 hi + 512 lo 16B-chunks (row = tt>>2, chunk = tt&3)
#pragma unroll
        for (int i = 0; i < 4; i++) {
            const int t  = tid + (i << 8);
            const int tt = t & 511;
            const int row = tt >> 2, ch = tt & 3;
            const __half* src = (t < 512) ? Ah : Al;
            const uint32_t off = (t < 512) ? 0u : (uint32_t)A_SZ;
            cp_async16(sb + (off + row * ASTR + ch * 8) * 2,
                       src + (size_t)(bm + row) * K + k0 + ch * 8);
        }
        // B: 512 hi + 512 lo 16B-chunks (k row = tt>>4, chunk = tt&15)
#pragma unroll
        for (int i = 4; i < 8; i++) {
            const int t  = tid + (i << 8);
            const int tt = t & 511;
            const int kr = tt >> 4, ch = tt & 15;
            const __half* src = (t < 1536) ? Bh : Bl;
            const uint32_t off = (t < 1536) ? (uint32_t)(2 * A_SZ)
                                            : (uint32_t)(2 * A_SZ + B_SZ);
            cp_async16(sb + (off + kr * BSTR + ch * 8) * 2,
                       src + (size_t)(k0 + kr) * N + bn + ch * 8);
        }
    };

    load_stage(0, 0);
    CP_COMMIT();

    // lane-specific ldmatrix addressing
    const int arow = lane & 15;
    const int ahk  = (lane >> 4) << 3;                   // A k offset 0/8
    const int bkr  = ((lane >> 3) & 1) * 8 + (lane & 7); // B k row
    const int bno  = (lane >> 4) << 3;                   // B n offset 0/8

    for (int c = 0; c < chunks; ++c) {
        const int s = c & 1;
        if (c + 1 < chunks) {
            load_stage(c + 1, s ^ 1);
            CP_COMMIT();
            CP_WAIT(1);
        } else {
            CP_WAIT(0);
        }
        __syncthreads();

        const uint32_t sb  = smb + (uint32_t)(s * STG * 2);
        const uint32_t sAh = sb;
        const uint32_t sBh = sb + (uint32_t)(2 * A_SZ * 2);
#pragma unroll
        for (int ks = 0; ks < 2; ks++) {
            const int kb = ks << 4;
            uint32_t b_h[2][4], b_l[2][4];
#pragma unroll
            for (int nj = 0; nj < 2; nj++) {
                const uint32_t bd = sBh +
                    (uint32_t)(((kb + bkr) * BSTR + nb + nj * 16 + bno) * 2);
                ldm_x4_t(b_h[nj], bd);
                ldm_x4_t(b_l[nj], bd + (uint32_t)(B_SZ * 2));
            }
#pragma unroll
            for (int mi = 0; mi < 4; mi++) {
                uint32_t a[4];
                const uint32_t ad = sAh +
                    (uint32_t)(((mb + mi * 16 + arow) * ASTR + kb + ahk) * 2);
                ldm_x4(a, ad);                           // Ah
#pragma unroll
                for (int ni = 0; ni < 4; ni++) {
                    const int nj = ni >> 1;
                    const int bi = (ni & 1) << 1;
                    MMA_F16(acc[mi][ni][0], acc[mi][ni][1],
                            acc[mi][ni][2], acc[mi][ni][3],
                            a[0], a[1], a[2], a[3],
                            b_h[nj][bi], b_h[nj][bi + 1]);
                    MMA_F16H(acc16[mi][ni][0], acc16[mi][ni][1],
                             a[0], a[1], a[2], a[3],
                             b_l[nj][bi], b_l[nj][bi + 1]);   // Ah*Bl
                }
                ldm_x4(a, ad + (uint32_t)(A_SZ * 2));    // Al
#pragma unroll
                for (int ni = 0; ni < 4; ni++) {
                    const int nj = ni >> 1;
                    const int bi = (ni & 1) << 1;
                    MMA_F16H(acc16[mi][ni][0], acc16[mi][ni][1],
                             a[0], a[1], a[2], a[3],
                             b_h[nj][bi], b_h[nj][bi + 1]);   // Al*Bh
                }
            }
        }
        __syncthreads();
    }

    // epilogue
#pragma unroll
    for (int mi = 0; mi < 4; mi++) {
        const int r0 = bm + mb + mi * 16 + grp;
        const int r1 = r0 + 8;
#pragma unroll
        for (int ni = 0; ni < 4; ni++) {
            const int cc = bn + nb + ni * 8 + qd * 2;
            const float2 cl0 = __half22float2(
                *reinterpret_cast<__half2*>(&acc16[mi][ni][0]));
            const float2 cl1 = __half22float2(
                *reinterpret_cast<__half2*>(&acc16[mi][ni][1]));
            float2 v0 = make_float2(acc[mi][ni][0] + cl0.x,
                                    acc[mi][ni][1] + cl0.y);
            float2 v1 = make_float2(acc[mi][ni][2] + cl1.x,
                                    acc[mi][ni][3] + cl1.y);
            if (BIAS) {
                const float2 bb = *reinterpret_cast<const float2*>(bias + cc);
                v0.x += bb.x; v0.y += bb.y; v1.x += bb.x; v1.y += bb.y;
            }
            if (GELU) {
                v0.x = 0.5f * v0.x * (1.f + erff(v0.x * 0.70710678118654752f));
                v0.y = 0.5f * v0.y * (1.f + erff(v0.y * 0.70710678118654752f));
                v1.x = 0.5f * v1.x * (1.f + erff(v1.x * 0.70710678118654752f));
                v1.y = 0.5f * v1.y * (1.f + erff(v1.y * 0.70710678118654752f));
            }
            if (RES) {
                const float2 ra = *reinterpret_cast<const float2*>(
                    res + (size_t)r0 * N + cc);
                const float2 rb = *reinterpret_cast<const float2*>(
                    res + (size_t)r1 * N + cc);
                v0.x += ra.x; v0.y += ra.y; v1.x += rb.x; v1.y += rb.y;
            }
            if (SPLITOUT) {
                __half h0, l0, h1, l1;
                h_split(v0.x, h0, l0); h_split(v0.y, h1, l1);
                *reinterpret_cast<__half2*>(Ch + (size_t)r0 * N + cc) =
                    __halves2half2(h0, h1);
                *reinterpret_cast<__half2*>(Cl + (size_t)r0 * N + cc) =
                    __halves2half2(l0, l1);
                h_split(v1.x, h0, l0); h_split(v1.y, h1, l1);
                *reinterpret_cast<__half2*>(Ch + (size_t)r1 * N + cc) =
                    __halves2half2(h0, h1);
                *reinterpret_cast<__half2*>(Cl + (size_t)r1 * N + cc) =
                    __halves2half2(l0, l1);
            } else {
                *reinterpret_cast<float2*>(C + (size_t)r0 * N + cc) = v0;
                *reinterpret_cast<float2*>(C + (size_t)r1 * N + cc) = v1;
            }
        }
    }
}

// ---------------------------------------------------------------------------
// Weight pre-split: fp32 -> (hi, lo) fp16 pair. n % 1024 == 0.
// ---------------------------------------------------------------------------
__global__ void wsplit_kernel(const float* __restrict__ w,
                              __half* __restrict__ wh,
                              __half* __restrict__ wl, int n)
{
    const int i = (blockIdx.x * 256 + threadIdx.x) * 4;
    if (i >= n) return;
    const float4 v = *reinterpret_cast<const float4*>(w + i);
    __half h0, l0, h1, l1, h2, l2, h3, l3;
    h_split(v.x, h0, l0); h_split(v.y, h1, l1);
    h_split(v.z, h2, l2); h_split(v.w, h3, l3);
    *reinterpret_cast<__half2*>(wh + i)     = __halves2half2(h0, h1);
    *reinterpret_cast<__half2*>(wh + i + 2) = __halves2half2(h2, h3);
    *reinterpret_cast<__half2*>(wl + i)     = __halves2half2(l0, l1);
    *reinterpret_cast<__half2*>(wl + i + 2) = __halves2half2(l2, l3);
}

// ---------------------------------------------------------------------------
// fp32 SGEMM (fx-update: K=64). 128x128x8 tile.
// ---------------------------------------------------------------------------
template <bool BIAS, bool RES, bool GELU>
__global__ void sgemm_kernel(const float* __restrict__ A,
                             const float* __restrict__ Bm,
                             float* __restrict__ C,
                             const float* __restrict__ bias,
                             const float* __restrict__ res,
                             int M, int K, int N,
                             long long sA, long long sB, long long sC, long long sR)
{
    const int bz = blockIdx.z;
    A  += (long long)bz * sA;
    Bm += (long long)bz * sB;
    C  += (long long)bz * sC;
    if (RES) res += (long long)bz * sR;

    __shared__ float As[8][128];
    __shared__ float Bs[8][128];

    const int tid  = threadIdx.x;
    const int brow = blockIdx.y * 128;
    const int bcol = blockIdx.x * 128;
    const int tx = tid & 15;
    const int ty = tid >> 4;
    const int arow = tid >> 1;
    const int acol = (tid & 1) << 2;
    const int brw  = tid >> 5;
    const int bcl  = (tid & 31) << 2;

    float acc[8][8];
#pragma unroll
    for (int i = 0; i < 8; i++)
#pragma unroll
        for (int j = 0; j < 8; j++) acc[i][j] = 0.f;

    for (int k0 = 0; k0 < K; k0 += 8) {
        float4 av = *reinterpret_cast<const float4*>(
            &A[(long long)(brow + arow) * K + k0 + acol]);
        As[acol + 0][arow] = av.x;
        As[acol + 1][arow] = av.y;
        As[acol + 2][arow] = av.z;
        As[acol + 3][arow] = av.w;
        if (bcol + bcl + 3 < N) {
            *reinterpret_cast<float4*>(&Bs[brw][bcl]) =
                *reinterpret_cast<const float4*>(
                    &Bm[(long long)(k0 + brw) * N + bcol + bcl]);
        } else {
#pragma unroll
            for (int j = 0; j < 4; j++)
                Bs[brw][bcl + j] = (bcol + bcl + j < N)
                    ? Bm[(long long)(k0 + brw) * N + bcol + bcl + j] : 0.f;
        }
        __syncthreads();
#pragma unroll
        for (int k = 0; k < 8; k++) {
            float ar[8], br[8];
            *reinterpret_cast<float4*>(&ar[0]) = *reinterpret_cast<const float4*>(&As[k][ty * 8]);
            *reinterpret_cast<float4*>(&ar[4]) = *reinterpret_cast<const float4*>(&As[k][ty * 8 + 4]);
            *reinterpret_cast<float4*>(&br[0]) = *reinterpret_cast<const float4*>(&Bs[k][tx * 8]);
            *reinterpret_cast<float4*>(&br[4]) = *reinterpret_cast<const float4*>(&Bs[k][tx * 8 + 4]);
#pragma unroll
            for (int i = 0; i < 8; i++)
#pragma unroll
                for (int j = 0; j < 8; j++)
                    acc[i][j] += ar[i] * br[j];
        }
        __syncthreads();
    }
#pragma unroll
    for (int i = 0; i < 8; i++) {
        const long long r = brow + ty * 8 + i;
#pragma unroll
        for (int j = 0; j < 8; j++) {
            const int c = bcol + tx * 8 + j;
            if (c < N) {
                float v = acc[i][j];
                if (BIAS) v += bias[c];
                if (GELU) v = 0.5f * v * (1.f + erff(v * 0.70710678118654752f));
                if (RES)  v += res[r * N + c];
                C[r * N + c] = v;
            }
        }
    }
}

// ---------------------------------------------------------------------------
// Split-K fp32 GEMM for step 10 (N=64): C[128,64] += A-chunk @ B-chunk.
// grid (1, M/128, ksplit). C zeroed beforehand; bias omitted (BN-invariant).
// ---------------------------------------------------------------------------
__global__ void sgemm_nk_splitk_kernel(const float* __restrict__ A,
                                       const float* __restrict__ Bm,
                                       float* __restrict__ C,
                                       int M, int K, int N, int ksplit)
{
    __shared__ float As[8][128];
    __shared__ float Bs[8][64];

    const int tid  = threadIdx.x;
    const int brow = blockIdx.y * 128;
    const int kchunk = K / ksplit;
    const int kbeg = blockIdx.z * kchunk;
    const int kend = kbeg + kchunk;

    const int tx = tid & 15;
    const int ty = tid >> 4;
    const int arow = tid >> 1;
    const int acol = (tid & 1) << 2;
    const int brw  = tid >> 5;
    const int bcl  = (tid & 31) << 1;

    float acc[8][4];
#pragma unroll
    for (int i = 0; i < 8; i++)
#pragma unroll
        for (int j = 0; j < 4; j++) acc[i][j] = 0.f;

    for (int k0 = kbeg; k0 < kend; k0 += 8) {
        float4 av = *reinterpret_cast<const float4*>(
            &A[(long long)(brow + arow) * K + k0 + acol]);
        As[acol + 0][arow] = av.x;
        As[acol + 1][arow] = av.y;
        As[acol + 2][arow] = av.z;
        As[acol + 3][arow] = av.w;
        *reinterpret_cast<float2*>(&Bs[brw][bcl]) =
            *reinterpret_cast<const float2*>(&Bm[(long long)(k0 + brw) * N + bcl]);
        __syncthreads();
#pragma unroll
        for (int k = 0; k < 8; k++) {
            float ar[8], br[4];
            *reinterpret_cast<float4*>(&ar[0]) = *reinterpret_cast<const float4*>(&As[k][ty * 8]);
            *reinterpret_cast<float4*>(&ar[4]) = *reinterpret_cast<const float4*>(&As[k][ty * 8 + 4]);
            *reinterpret_cast<float4*>(&br[0]) = *reinterpret_cast<const float4*>(&Bs[k][tx * 4]);
#pragma unroll
            for (int i = 0; i < 8; i++)
#pragma unroll
                for (int j = 0; j < 4; j++)
                    acc[i][j] += ar[i] * br[j];
        }
        __syncthreads();
    }
#pragma unroll
    for (int i = 0; i < 8; i++) {
        const long long r = brow + ty * 8 + i;
#pragma unroll
        for (int j = 0; j < 4; j++)
            atomicAdd(&C[r * N + tx * 4 + j], acc[i][j]);
    }
}

// ---------------------------------------------------------------------------
// Split-K A^T B with atomic accumulation (C zeroed beforehand).
// ---------------------------------------------------------------------------
__global__ void atb_split_kernel(const float* __restrict__ A,
                                 const float* __restrict__ Bm,
                                 float* __restrict__ C,
                                 int K, int N, int lda, int ldb, int ldc,
                                 long long sA, long long sB, long long sC,
                                 float scale, int ksplit)
{
    const int bz = blockIdx.y;
    A  += (long long)bz * sA;
    Bm += (long long)bz * sB;
    C  += (long long)bz * sC;
    const int bcol = blockIdx.x * 64;
    const int kchunk = K / ksplit;
    const int kbeg = blockIdx.z * kchunk;
    const int kend = kbeg + kchunk;

    __shared__ float As[16][64];
    __shared__ float Bs[16][64];

    const int t  = threadIdx.x;
    const int kk = t >> 4;
    const int c4 = (t & 15) << 2;
    const int ty = t >> 4;
    const int tx = t & 15;

    float acc[4][4];
#pragma unroll
    for (int i = 0; i < 4; i++)
#pragma unroll
        for (int j = 0; j < 4; j++) acc[i][j] = 0.f;

    for (int k0 = kbeg; k0 < kend; k0 += 16) {
        *reinterpret_cast<float4*>(&As[kk][c4]) =
            *reinterpret_cast<const float4*>(&A[(long long)(k0 + kk) * lda + c4]);
        *reinterpret_cast<float4*>(&Bs[kk][c4]) =
            *reinterpret_cast<const float4*>(&Bm[(long long)(k0 + kk) * ldb + bcol + c4]);
        __syncthreads();
#pragma unroll
        for (int k = 0; k < 16; k++) {
            float ar[4], br[4];
            *reinterpret_cast<float4*>(ar) = *reinterpret_cast<const float4*>(&As[k][ty * 4]);
            *reinterpret_cast<float4*>(br) = *reinterpret_cast<const float4*>(&Bs[k][tx * 4]);
#pragma unroll
            for (int i = 0; i < 4; i++)
#pragma unroll
                for (int j = 0; j < 4; j++)
                    acc[i][j] += ar[i] * br[j];
        }
        __syncthreads();
    }
#pragma unroll
    for (int i = 0; i < 4; i++)
#pragma unroll
        for (int j = 0; j < 4; j++)
            atomicAdd(&C[(long long)(ty * 4 + i) * ldc + bcol + tx * 4 + j],
                      acc[i][j] * scale);
}

// ---------------------------------------------------------------------------
// attn apply: per (b,h): attn[n,:] = q[n,:] @ dots[b,h] -> split-fp16 output
// ---------------------------------------------------------------------------
__global__ void attn_kernel(const float* __restrict__ qkv,
                            const float* __restrict__ dots,
                            __half* __restrict__ outh,
                            __half* __restrict__ outl)
{
    const int bh = blockIdx.y;
    const int b  = bh >> 4;
    const int h  = bh & 15;
    const float* q = qkv + (long long)b * SEQ * (3 * HID) + h * DH;
    const float* D = dots + (long long)bh * DH * DH;
    const long long cbase = (long long)b * SEQ * HID + h * DH;
    const int row0 = blockIdx.x * 64;

    __shared__ float As[16][64];
    __shared__ float Bs[16][64];

    const int t   = threadIdx.x;
    const int ty  = t >> 4;
    const int tx  = t & 15;
    const int lm  = t >> 2;
    const int lk4 = (t & 3) << 2;
    const int bk  = t >> 4;
    const int bn4 = (t & 15) << 2;

    float acc[4][4];
#pragma unroll
    for (int i = 0; i < 4; i++)
#pragma unroll
        for (int j = 0; j < 4; j++) acc[i][j] = 0.f;

    for (int k0 = 0; k0 < DH; k0 += 16) {
        float4 av = *reinterpret_cast<const float4*>(
            &q[(long long)(row0 + lm) * (3 * HID) + k0 + lk4]);
        As[lk4 + 0][lm] = av.x;
        As[lk4 + 1][lm] = av.y;
        As[lk4 + 2][lm] = av.z;
        As[lk4 + 3][lm] = av.w;
        *reinterpret_cast<float4*>(&Bs[bk][bn4]) =
            *reinterpret_cast<const float4*>(&D[(k0 + bk) * DH + bn4]);
        __syncthreads();
#pragma unroll
        for (int k = 0; k < 16; k++) {
            float ar[4], br[4];
            *reinterpret_cast<float4*>(ar) = *reinterpret_cast<const float4*>(&As[k][ty * 4]);
            *reinterpret_cast<float4*>(br) = *reinterpret_cast<const float4*>(&Bs[k][tx * 4]);
#pragma unroll
            for (int i = 0; i < 4; i++)
#pragma unroll
                for (int j = 0; j < 4; j++)
                    acc[i][j] += ar[i] * br[j];
        }
        __syncthreads();
    }
#pragma unroll
    for (int i = 0; i < 4; i++)
#pragma unroll
        for (int j = 0; j < 4; j += 2) {
            const long long idx = cbase +
                (long long)(row0 + ty * 4 + i) * HID + tx * 4 + j;
            __half h0, l0, h1, l1;
            h_split(acc[i][j],     h0, l0);
            h_split(acc[i][j + 1], h1, l1);
            *reinterpret_cast<__half2*>(outh + idx) = __halves2half2(h0, h1);
            *reinterpret_cast<__half2*>(outl + idx) = __halves2half2(l0, l1);
        }
}

// ---------------------------------------------------------------------------
// Row LayerNorm over H=1024 with split-fp16 output
// ---------------------------------------------------------------------------
__global__ void ln_split_kernel(const float* __restrict__ x,
                                const float* __restrict__ g,
                                const float* __restrict__ b,
                                __half* __restrict__ yh,
                                __half* __restrict__ yl)
{
    const int row = blockIdx.x;
    const float4 v = reinterpret_cast<const float4*>(x + (long long)row * HID)[threadIdx.x];
    float s  = v.x + v.y + v.z + v.w;
    float sq = v.x * v.x + v.y * v.y + v.z * v.z + v.w * v.w;
#pragma unroll
    for (int o = 16; o; o >>= 1) {
        s  += __shfl_xor_sync(0xffffffffu, s,  o);
        sq += __shfl_xor_sync(0xffffffffu, sq, o);
    }
    __shared__ float ss[8], ssq[8];
    const int w = threadIdx.x >> 5, l = threadIdx.x & 31;
    if (l == 0) { ss[w] = s; ssq[w] = sq; }
    __syncthreads();
    if (w == 0) {
        s  = (l < 8) ? ss[l]  : 0.f;
        sq = (l < 8) ? ssq[l] : 0.f;
#pragma unroll
        for (int o = 4; o; o >>= 1) {
            s  += __shfl_xor_sync(0xffffffffu, s,  o);
            sq += __shfl_xor_sync(0xffffffffu, sq, o);
        }
        if (l == 0) { ss[0] = s; ssq[0] = sq; }
    }
    __syncthreads();
    const float mean = ss[0] * (1.f / HID);
    const float var  = ssq[0] * (1.f / HID) - mean * mean;
    const float rstd = rsqrtf(var + EPSV);
    const float4 gg = reinterpret_cast<const float4*>(g)[threadIdx.x];
    const float4 bb = reinterpret_cast<const float4*>(b)[threadIdx.x];
    float o0 = (v.x - mean) * rstd * gg.x + bb.x;
    float o1 = (v.y - mean) * rstd * gg.y + bb.y;
    float o2 = (v.z - mean) * rstd * gg.z + bb.z;
    float o3 = (v.w - mean) * rstd * gg.w + bb.w;
    __half h0, l0, h1, l1, h2, l2, h3, l3;
    h_split(o0, h0, l0); h_split(o1, h1, l1);
    h_split(o2, h2, l2); h_split(o3, h3, l3);
    const long long base = (long long)row * HID + threadIdx.x * 4;
    *reinterpret_cast<__half2*>(yh + base)     = __halves2half2(h0, h1);
    *reinterpret_cast<__half2*>(yh + base + 2) = __halves2half2(h2, h3);
    *reinterpret_cast<__half2*>(yl + base)     = __halves2half2(l0, l1);
    *reinterpret_cast<__half2*>(yl + base + 2) = __halves2half2(l2, l3);
}

// ---------------------------------------------------------------------------
// k/v LayerNorm over DH=64 per (token, head) -> [b][h][n][d] layout
// ---------------------------------------------------------------------------
__global__ void kvln_kernel(const float* __restrict__ qkv,
                            const float* __restrict__ kg, const float* __restrict__ kb,
                            const float* __restrict__ vg, const float* __restrict__ vb,
                            float* __restrict__ kn, float* __restrict__ vn)
{
    const long long r = (long long)blockIdx.x * 8 + (threadIdx.x >> 5);
    const int lane = threadIdx.x & 31;
    const int bh = (int)(r >> 12);
    const int n  = (int)(r & 4095);
    const int b  = bh >> 4;
    const int h  = bh & 15;
    const float* base = qkv + ((long long)(b * SEQ + n)) * (3 * HID) + h * DH;
    const float2 kv = *reinterpret_cast<const float2*>(base + HID     + lane * 2);
    const float2 vv = *reinterpret_cast<const float2*>(base + 2 * HID + lane * 2);
    float s1 = kv.x + kv.y, q1 = kv.x * kv.x + kv.y * kv.y;
    float s2 = vv.x + vv.y, q2 = vv.x * vv.x + vv.y * vv.y;
#pragma unroll
    for (int o = 16; o; o >>= 1) {
        s1 += __shfl_xor_sync(0xffffffffu, s1, o);
        q1 += __shfl_xor_sync(0xffffffffu, q1, o);
        s2 += __shfl_xor_sync(0xffffffffu, s2, o);
        q2 += __shfl_xor_sync(0xffffffffu, q2, o);
    }
    const float m1 = s1 * (1.f / DH), rs1 = rsqrtf(q1 * (1.f / DH) - m1 * m1 + EPSV);
    const float m2 = s2 * (1.f / DH), rs2 = rsqrtf(q2 * (1.f / DH) - m2 * m2 + EPSV);
    const int d = lane * 2;
    float2 ko, vo;
    ko.x = (kv.x - m1) * rs1 * kg[d]     + kb[d];
    ko.y = (kv.y - m1) * rs1 * kg[d + 1] + kb[d + 1];
    vo.x = (vv.x - m2) * rs2 * vg[d]     + vb[d];
    vo.y = (vv.y - m2) * rs2 * vg[d + 1] + vb[d + 1];
    *reinterpret_cast<float2*>(kn + r * DH + d) = ko;
    *reinterpret_cast<float2*>(vn + r * DH + d) = vo;
}

// ---------------------------------------------------------------------------
// BatchNorm1d (training stats) + softplus(mu) scaling
// ---------------------------------------------------------------------------
__global__ void bn_stats_kernel(const float* __restrict__ xp, float* __restrict__ stats)
{
    const int p = blockIdx.x;
    float s = 0.f, sq = 0.f;
    for (int r = threadIdx.x; r < MROWS; r += 256) {
        const float v = xp[(long long)r * PSI + p];
        s += v; sq += v * v;
    }
#pragma unroll
    for (int o = 16; o; o >>= 1) {
        s  += __shfl_xor_sync(0xffffffffu, s,  o);
        sq += __shfl_xor_sync(0xffffffffu, sq, o);
    }
    __shared__ float ss[8], ssq[8];
    const int w = threadIdx.x >> 5, l = threadIdx.x & 31;
    if (l == 0) { ss[w] = s; ssq[w] = sq; }
    __syncthreads();
    if (threadIdx.x == 0) {
        float ts = 0.f, tq = 0.f;
        for (int i = 0; i < 8; i++) { ts += ss[i]; tq += ssq[i]; }
        const float mean = ts * (1.f / MROWS);
        const float var  = tq * (1.f / MROWS) - mean * mean;
        stats[p]       = mean;
        stats[PSI + p] = rsqrtf(var + EPSV);
    }
}

__global__ void bn_apply_kernel(const float* __restrict__ xp,
                                const float* __restrict__ stats,
                                const float* __restrict__ bng,
                                const float* __restrict__ bnb,
                                const float* __restrict__ mu,
                                float* __restrict__ xn,
                                float* __restrict__ xs)
{
    const long long i = (long long)blockIdx.x * 256 + threadIdx.x;
    const int p = (int)(i & (PSI - 1));
    const float v = (xp[i] - stats[p]) * stats[PSI + p] * bng[p] + bnb[p];
    xn[i] = v;
    const float m = mu[p];
    const float sp = (m > 20.f) ? m : log1pf(expf(m));
    xs[i] = v * sp;
}

// ---------------------------------------------------------------------------
// Launch
// ---------------------------------------------------------------------------
extern "C" void kernel_launch(void* const* d_in, const int* in_sizes, int n_in,
                              void* d_out, int out_size)
{
    const float* x    = (const float*)d_in[0];
    const float* fx   = (const float*)d_in[1];
    const float* mu   = (const float*)d_in[2];
    const float* ln1g = (const float*)d_in[3];
    const float* ln1b = (const float*)d_in[4];
    const float* Wqkv = (const float*)d_in[5];
    const float* kg   = (const float*)d_in[6];
    const float* kb   = (const float*)d_in[7];
    const float* vg   = (const float*)d_in[8];
    const float* vb   = (const float*)d_in[9];
    const float* Wout = (const float*)d_in[10];
    const float* bout = (const float*)d_in[11];
    const float* ln2g = (const float*)d_in[12];
    const float* ln2b = (const float*)d_in[13];
    const float* W1   = (const float*)d_in[14];
    const float* b1   = (const float*)d_in[15];
    const float* W2   = (const float*)d_in[16];
    const float* b2   = (const float*)d_in[17];
    const float* Wp   = (const float*)d_in[18];
    const float* bp   = (const float*)d_in[19];  // BN-invariant; unused
    const float* bng  = (const float*)d_in[20];
    const float* bnb  = (const float*)d_in[21];
    const float* ln3g = (const float*)d_in[22];
    const float* ln3b = (const float*)d_in[23];
    const float* W3   = (const float*)d_in[24];
    const float* b3   = (const float*)d_in[25];
    const float* W4   = (const float*)d_in[26];
    const float* b4   = (const float*)d_in[27];
    (void)bp;

    float* outx  = (float*)d_out;
    float* outfx = outx + (long long)MROWS * HID;

    float *p_qkv, *p_kn, *p_vn, *p_dots, *p_x1;
    float *p_xp, *p_xn, *p_xs, *p_stats, *p_kern, *p_fx1;
    __half *p_wh, *p_wl, *p_lnh, *p_lnl, *p_atth, *p_attl, *p_midh, *p_midl;
    cudaGetSymbolAddress((void**)&p_qkv,  g_qkv);
    cudaGetSymbolAddress((void**)&p_kn,   g_kn);
    cudaGetSymbolAddress((void**)&p_vn,   g_vn);
    cudaGetSymbolAddress((void**)&p_dots, g_dots);
    cudaGetSymbolAddress((void**)&p_x1,   g_x1);
    cudaGetSymbolAddress((void**)&p_xp,   g_xp);
    cudaGetSymbolAddress((void**)&p_xn,   g_xn);
    cudaGetSymbolAddress((void**)&p_xs,   g_xs);
    cudaGetSymbolAddress((void**)&p_stats,g_stats);
    cudaGetSymbolAddress((void**)&p_kern, g_kern);
    cudaGetSymbolAddress((void**)&p_fx1,  g_fx1);
    cudaGetSymbolAddress((void**)&p_wh,   g_wh);
    cudaGetSymbolAddress((void**)&p_wl,   g_wl);
    cudaGetSymbolAddress((void**)&p_lnh,  g_lnh);
    cudaGetSymbolAddress((void**)&p_lnl,  g_lnl);
    cudaGetSymbolAddress((void**)&p_atth, g_atth);
    cudaGetSymbolAddress((void**)&p_attl, g_attl);
    cudaGetSymbolAddress((void**)&p_midh, g_midh);
    cudaGetSymbolAddress((void**)&p_midl, g_midl);

    cudaFuncSetAttribute(h16_gemm_kernel<false, false, false, false>,
                         cudaFuncAttributeMaxDynamicSharedMemorySize, H16_SMEM_BYTES);
    cudaFuncSetAttribute(h16_gemm_kernel<true, true, false, false>,
                         cudaFuncAttributeMaxDynamicSharedMemorySize, H16_SMEM_BYTES);
    cudaFuncSetAttribute(h16_gemm_kernel<true, false, true, true>,
                         cudaFuncAttributeMaxDynamicSharedMemorySize, H16_SMEM_BYTES);
    cudaFuncSetAttribute(h16_gemm_kernel<true, false, false, false>,
                         cudaFuncAttributeMaxDynamicSharedMemorySize, H16_SMEM_BYTES);

    // 0) pre-split all weights to fp16 pairs
    wsplit_kernel<<<(HID * 3 * HID) / 1024, 256>>>(Wqkv, p_wh + OFF_QKV,  p_wl + OFF_QKV,  HID * 3 * HID);
    wsplit_kernel<<<(HID * HID)     / 1024, 256>>>(Wout, p_wh + OFF_WOUT, p_wl + OFF_WOUT, HID * HID);
    wsplit_kernel<<<(HID * 4 * HID) / 1024, 256>>>(W1,   p_wh + OFF_W1,   p_wl + OFF_W1,   HID * 4 * HID);
    wsplit_kernel<<<(4 * HID * HID) / 1024, 256>>>(W2,   p_wh + OFF_W2,   p_wl + OFF_W2,   4 * HID * HID);
    wsplit_kernel<<<(HID * 4 * HID) / 1024, 256>>>(W3,   p_wh + OFF_W3,   p_wl + OFF_W3,   HID * 4 * HID);
    wsplit_kernel<<<(4 * HID * HID) / 1024, 256>>>(W4,   p_wh + OFF_W4,   p_wl + OFF_W4,   4 * HID * HID);

    // 1) h = LN1(x) -> split
    ln_split_kernel<<<MROWS, 256>>>(x, ln1g, ln1b, p_lnh, p_lnl);
    // 2) qkv = h @ Wqkv
    h16_gemm_kernel<false, false, false, false><<<dim3(24, 128), 256, H16_SMEM_BYTES>>>(
        p_lnh, p_lnl, p_wh + OFF_QKV, p_wl + OFF_QKV,
        p_qkv, nullptr, nullptr, nullptr, nullptr, MROWS, HID, 3 * HID);
    // 3) LN(k), LN(v)
    kvln_kernel<<<(Bq * NHEAD * SEQ) / 8, 256>>>(p_qkv, kg, kb, vg, vb, p_kn, p_vn);
    // 4) dots = k^T v / N
    cudaMemsetAsync(p_dots, 0, sizeof(float) * Bq * NHEAD * DH * DH);
    atb_split_kernel<<<dim3(1, Bq * NHEAD, 16), 256>>>(
        p_kn, p_vn, p_dots, SEQ, DH, DH, DH, DH,
        (long long)SEQ * DH, (long long)SEQ * DH, (long long)DH * DH,
        1.f / (float)SEQ, 16);
    // 5) attn = q @ dots -> split
    attn_kernel<<<dim3(SEQ / 64, Bq * NHEAD), 256>>>(p_qkv, p_dots, p_atth, p_attl);
    // 6) x1 = attn @ Wout + bout + x
    h16_gemm_kernel<true, true, false, false><<<dim3(8, 128), 256, H16_SMEM_BYTES>>>(
        p_atth, p_attl, p_wh + OFF_WOUT, p_wl + OFF_WOUT,
        p_x1, nullptr, nullptr, bout, x, MROWS, HID, HID);
    // 7) h = LN2(x1) -> split
    ln_split_kernel<<<MROWS, 256>>>(p_x1, ln2g, ln2b, p_lnh, p_lnl);
    // 8) mid = gelu(h @ W1 + b1) -> split
    h16_gemm_kernel<true, false, true, true><<<dim3(32, 128), 256, H16_SMEM_BYTES>>>(
        p_lnh, p_lnl, p_wh + OFF_W1, p_wl + OFF_W1,
        nullptr, p_midh, p_midl, b1, nullptr, MROWS, HID, 4 * HID);
    // 9) x_out = mid @ W2 + b2 + x1 -> d_out first half
    h16_gemm_kernel<true, true, false, false><<<dim3(8, 128), 256, H16_SMEM_BYTES>>>(
        p_midh, p_midl, p_wh + OFF_W2, p_wl + OFF_W2,
        outx, nullptr, nullptr, b2, p_x1, MROWS, 4 * HID, HID);
    // 10) xp = x_out @ Wp (bias bp cancels in BN) -- split-K x8, atomics
    cudaMemsetAsync(p_xp, 0, sizeof(float) * MROWS * PSI);
    sgemm_nk_splitk_kernel<<<dim3(1, MROWS / 128, 8), 256>>>(
        outx, Wp, p_xp, MROWS, HID, PSI, 8);
    // 11-12) BatchNorm + softplus scaling
    bn_stats_kernel<<<PSI, 256>>>(p_xp, p_stats);
    bn_apply_kernel<<<(MROWS * PSI) / 256, 256>>>(p_xp, p_stats, bng, bnb, mu, p_xn, p_xs);
    // 13) kern = x_^T @ fx per batch
    cudaMemsetAsync(p_kern, 0, sizeof(float) * Bq * PSI * HID);
    atb_split_kernel<<<dim3(HID / 64, Bq, 16), 256>>>(
        p_xn, fx, p_kern, SEQ, HID, PSI, HID, HID,
        (long long)SEQ * PSI, (long long)SEQ * HID, (long long)PSI * HID, 1.f, 16);
    // 14) fx1 = (x_ * sp(mu)) @ kern + fx per batch (fp32, K=64)
    sgemm_kernel<false, true, false><<<dim3(8, 32, Bq), 256>>>(
        p_xs, p_kern, p_fx1, nullptr, fx, SEQ, PSI, HID,
        (long long)SEQ * PSI, (long long)PSI * HID,
        (long long)SEQ * HID, (long long)SEQ * HID);
    // 15) h = LN3(fx1) -> split
    ln_split_kernel<<<MROWS, 256>>>(p_fx1, ln3g, ln3b, p_lnh, p_lnl);
    // 16) mid = gelu(h @ W3 + b3) -> split
    h16_gemm_kernel<true, false, true, true><<<dim3(32, 128), 256, H16_SMEM_BYTES>>>(
        p_lnh, p_lnl, p_wh + OFF_W3, p_wl + OFF_W3,
        nullptr, p_midh, p_midl, b3, nullptr, MROWS, HID, 4 * HID);
    // 17) fx_out = mid @ W4 + b4 -> d_out second half
    h16_gemm_kernel<true, false, false, false><<<dim3(8, 128), 256, H16_SMEM_BYTES>>>(
        p_midh, p_midl, p_wh + OFF_W4, p_wl + OFF_W4,
        outfx, nullptr, nullptr, b4, nullptr, MROWS, 4 * HID, HID);
}

// round 15
// speedup vs baseline: 1.1017x; 1.1017x over previous
#include <cuda_runtime.h>
#include <cuda_fp16.h>
#include <math.h>
#include <stdint.h>

// ---------------------------------------------------------------------------
// Problem constants: B=4, N=4096, H=1024, HEADS=16, DH=64, PSI=64, M=B*N=16384
// ---------------------------------------------------------------------------
#define Bq    4
#define SEQ   4096
#define HID   1024
#define NHEAD 16
#define DH    64
#define PSI   64
#define MROWS (Bq * SEQ)
#define EPSV  1e-5f

// Weight offsets in the packed split-weight buffers (element counts)
#define OFF_QKV  0
#define OFF_WOUT 3145728
#define OFF_W1   4194304
#define OFF_W2   8388608
#define OFF_W3   12582912
#define OFF_W4   16777216
#define WTOT     20971520

// ---------------------------------------------------------------------------
// Static device scratch
// ---------------------------------------------------------------------------
__device__ float  g_qkv [MROWS * 3 * HID];
__device__ float  g_kn  [MROWS * HID];
__device__ float  g_vn  [MROWS * HID];
__device__ float  g_dots[Bq * NHEAD * DH * DH];
__device__ float  g_x1  [MROWS * HID];
__device__ float  g_xp  [MROWS * PSI];
__device__ float  g_xn  [MROWS * PSI];
__device__ float  g_xs  [MROWS * PSI];
__device__ float  g_stats[2 * PSI];
__device__ float  g_psum [2 * PSI];
__device__ float  g_kern[Bq * PSI * HID];
__device__ float  g_fx1 [MROWS * HID];
// split-fp16 operand buffers
__device__ __half g_wh  [WTOT];
__device__ __half g_wl  [WTOT];
__device__ __half g_lnh [MROWS * HID];
__device__ __half g_lnl [MROWS * HID];
__device__ __half g_atth[MROWS * HID];
__device__ __half g_attl[MROWS * HID];
__device__ __half g_midh[MROWS * 4 * HID];
__device__ __half g_midl[MROWS * 4 * HID];

// ---------------------------------------------------------------------------
// PTX helpers
// ---------------------------------------------------------------------------
__device__ __forceinline__ void cp_async16(uint32_t dst, const void* src) {
    asm volatile("cp.async.cg.shared.global [%0], [%1], 16;"
                 :: "r"(dst), "l"(src));
}
#define CP_COMMIT()  asm volatile("cp.async.commit_group;")
#define CP_WAIT(n)   asm volatile("cp.async.wait_group %0;" :: "n"(n))

__device__ __forceinline__ void ldm_x4(uint32_t* r, uint32_t addr) {
    asm volatile("ldmatrix.sync.aligned.m8n8.x4.shared.b16 {%0,%1,%2,%3}, [%4];"
                 : "=r"(r[0]), "=r"(r[1]), "=r"(r[2]), "=r"(r[3]) : "r"(addr));
}
__device__ __forceinline__ void ldm_x4_t(uint32_t* r, uint32_t addr) {
    asm volatile("ldmatrix.sync.aligned.m8n8.x4.trans.shared.b16 {%0,%1,%2,%3}, [%4];"
                 : "=r"(r[0]), "=r"(r[1]), "=r"(r[2]), "=r"(r[3]) : "r"(addr));
}
#define MMA_F16(c0,c1,c2,c3,a0,a1,a2,a3,b0,b1)                              \
    asm volatile("mma.sync.aligned.m16n8k16.row.col.f32.f16.f16.f32 "       \
                 "{%0,%1,%2,%3}, {%4,%5,%6,%7}, {%8,%9}, {%0,%1,%2,%3};"    \
                 : "+f"(c0), "+f"(c1), "+f"(c2), "+f"(c3)                   \
                 : "r"(a0), "r"(a1), "r"(a2), "r"(a3), "r"(b0), "r"(b1))

// fp16 Dekker split: v ~= hi + lo (pair carries ~22 mantissa bits)
__device__ __forceinline__ void h_split(float v, __half& hi, __half& lo) {
    const __half h = __float2half_rn(v);
    hi = h;
    lo = __float2half_rn(v - __half2float(h));
}

// ---------------------------------------------------------------------------
// Split-fp16 GEMM (R12 winning config): C = (Ah+Al) @ (Bh+Bl) (+bias)(+gelu)
// (+res). acc += Ah*Bh + Al*Bh + Ah*Bl. Tile 128x128x32, 256 threads
// (2x4 warps, warp 64x32), 2-stage cp.async, 2 CTAs/SM.
// M%128==0, N%128==0, K%32==0.
// ---------------------------------------------------------------------------
#define ASTR 40                          // halves per A row (32 + 8 pad)
#define BSTR 136                         // halves per B row (128 + 8 pad)
#define A_SZ (128 * ASTR)                // 5120 halves
#define B_SZ (32 * BSTR)                 // 4352 halves
#define STG  (2 * A_SZ + 2 * B_SZ)       // 18944 halves per stage
#define H16_SMEM_BYTES (2 * STG * 2)     // 75776 bytes -> 2 CTAs/SM

template <bool BIAS, bool RES, bool GELU, bool SPLITOUT>
__global__ void __launch_bounds__(256, 2) h16_gemm_kernel(
    const __half* __restrict__ Ah, const __half* __restrict__ Al,
    const __half* __restrict__ Bh, const __half* __restrict__ Bl,
    float* __restrict__ C, __half* __restrict__ Ch, __half* __restrict__ Cl,
    const float* __restrict__ bias, const float* __restrict__ res,
    int M, int K, int N)
{
    extern __shared__ __half hsm[];
    const uint32_t smb = (uint32_t)__cvta_generic_to_shared(hsm);

    const int tid  = threadIdx.x;
    const int w    = tid >> 5;
    const int lane = tid & 31;
    const int grp  = lane >> 2;
    const int qd   = lane & 3;
    const int wm   = w >> 2;             // 0..1
    const int wn   = w & 3;              // 0..3
    const int mb   = wm * 64;
    const int nb   = wn * 32;

    const int bm = blockIdx.y * 128;
    const int bn = blockIdx.x * 128;

    float acc[4][4][4];
#pragma unroll
    for (int mi = 0; mi < 4; mi++)
#pragma unroll
        for (int ni = 0; ni < 4; ni++)
#pragma unroll
            for (int r = 0; r < 4; r++) acc[mi][ni][r] = 0.f;

    const int chunks = K >> 5;

    auto load_stage = [&](int c, int s) {
        const int k0 = c << 5;
        const uint32_t sb = smb + (uint32_t)(s * STG * 2);
        // A: 512 hi + 512 lo 16B-chunks (row = tt>>2, chunk = tt&3)
#pragma unroll
        for (int i = 0; i < 4; i++) {
            const int t  = tid + (i << 8);
            const int tt = t & 511;
            const int row = tt >> 2, ch = tt & 3;
            const __half* src = (t < 512) ? Ah : Al;
            const uint32_t off = (t < 512) ? 0u : (uint32_t)A_SZ;
            cp_async16(sb + (off + row * ASTR + ch * 8) * 2,
                       src + (size_t)(bm + row) * K + k0 + ch * 8);
        }
        // B: 512 hi + 512 lo 16B-chunks (k row = tt>>4, chunk = tt&15)
#pragma unroll
        for (int i = 4; i < 8; i++) {
            const int t  = tid + (i << 8);
            const int tt = t & 511;
            const int kr = tt >> 4, ch = tt & 15;
            const __half* src = (t < 1536) ? Bh : Bl;
            const uint32_t off = (t < 1536) ? (uint32_t)(2 * A_SZ)
                                            : (uint32_t)(2 * A_SZ + B_SZ);
            cp_async16(sb + (off + kr * BSTR + ch * 8) * 2,
                       src + (size_t)(k0 + kr) * N + bn + ch * 8);
        }
    };

    load_stage(0, 0);
    CP_COMMIT();

    // lane-specific ldmatrix addressing
    const int arow = lane & 15;
    const int ahk  = (lane >> 4) << 3;                   // A k offset 0/8
    const int bkr  = ((lane >> 3) & 1) * 8 + (lane & 7); // B k row
    const int bno  = (lane >> 4) << 3;                   // B n offset 0/8

    for (int c = 0; c < chunks; ++c) {
        const int s = c & 1;
        if (c + 1 < chunks) {
            load_stage(c + 1, s ^ 1);
            CP_COMMIT();
            CP_WAIT(1);
        } else {
            CP_WAIT(0);
        }
        __syncthreads();

        const uint32_t sb  = smb + (uint32_t)(s * STG * 2);
        const uint32_t sAh = sb;
        const uint32_t sBh = sb + (uint32_t)(2 * A_SZ * 2);
#pragma unroll
        for (int ks = 0; ks < 2; ks++) {
            const int kb = ks << 4;
            uint32_t a_h[4][4], a_l[4][4];
#pragma unroll
            for (int mi = 0; mi < 4; mi++) {
                const uint32_t ad = sAh +
                    (uint32_t)(((mb + mi * 16 + arow) * ASTR + kb + ahk) * 2);
                ldm_x4(a_h[mi], ad);
                ldm_x4(a_l[mi], ad + (uint32_t)(A_SZ * 2));
            }
            uint32_t b_h[2][4], b_l[2][4];
#pragma unroll
            for (int nj = 0; nj < 2; nj++) {
                const uint32_t bd = sBh +
                    (uint32_t)(((kb + bkr) * BSTR + nb + nj * 16 + bno) * 2);
                ldm_x4_t(b_h[nj], bd);
                ldm_x4_t(b_l[nj], bd + (uint32_t)(B_SZ * 2));
            }
#pragma unroll
            for (int mi = 0; mi < 4; mi++)
#pragma unroll
                for (int ni = 0; ni < 4; ni++) {
                    const int nj = ni >> 1;
                    const int bi = (ni & 1) << 1;
                    MMA_F16(acc[mi][ni][0], acc[mi][ni][1],
                            acc[mi][ni][2], acc[mi][ni][3],
                            a_h[mi][0], a_h[mi][1], a_h[mi][2], a_h[mi][3],
                            b_h[nj][bi], b_h[nj][bi + 1]);
                    MMA_F16(acc[mi][ni][0], acc[mi][ni][1],
                            acc[mi][ni][2], acc[mi][ni][3],
                            a_l[mi][0], a_l[mi][1], a_l[mi][2], a_l[mi][3],
                            b_h[nj][bi], b_h[nj][bi + 1]);
                    MMA_F16(acc[mi][ni][0], acc[mi][ni][1],
                            acc[mi][ni][2], acc[mi][ni][3],
                            a_h[mi][0], a_h[mi][1], a_h[mi][2], a_h[mi][3],
                            b_l[nj][bi], b_l[nj][bi + 1]);
                }
        }
        __syncthreads();
    }

    // epilogue
#pragma unroll
    for (int mi = 0; mi < 4; mi++) {
        const int r0 = bm + mb + mi * 16 + grp;
        const int r1 = r0 + 8;
#pragma unroll
        for (int ni = 0; ni < 4; ni++) {
            const int cc = bn + nb + ni * 8 + qd * 2;
            float2 v0 = make_float2(acc[mi][ni][0], acc[mi][ni][1]);
            float2 v1 = make_float2(acc[mi][ni][2], acc[mi][ni][3]);
            if (BIAS) {
                const float2 bb = *reinterpret_cast<const float2*>(bias + cc);
                v0.x += bb.x; v0.y += bb.y; v1.x += bb.x; v1.y += bb.y;
            }
            if (GELU) {
                v0.x = 0.5f * v0.x * (1.f + erff(v0.x * 0.70710678118654752f));
                v0.y = 0.5f * v0.y * (1.f + erff(v0.y * 0.70710678118654752f));
                v1.x = 0.5f * v1.x * (1.f + erff(v1.x * 0.70710678118654752f));
                v1.y = 0.5f * v1.y * (1.f + erff(v1.y * 0.70710678118654752f));
            }
            if (RES) {
                const float2 ra = *reinterpret_cast<const float2*>(
                    res + (size_t)r0 * N + cc);
                const float2 rb = *reinterpret_cast<const float2*>(
                    res + (size_t)r1 * N + cc);
                v0.x += ra.x; v0.y += ra.y; v1.x += rb.x; v1.y += rb.y;
            }
            if (SPLITOUT) {
                __half h0, l0, h1, l1;
                h_split(v0.x, h0, l0); h_split(v0.y, h1, l1);
                *reinterpret_cast<__half2*>(Ch + (size_t)r0 * N + cc) =
                    __halves2half2(h0, h1);
                *reinterpret_cast<__half2*>(Cl + (size_t)r0 * N + cc) =
                    __halves2half2(l0, l1);
                h_split(v1.x, h0, l0); h_split(v1.y, h1, l1);
                *reinterpret_cast<__half2*>(Ch + (size_t)r1 * N + cc) =
                    __halves2half2(h0, h1);
                *reinterpret_cast<__half2*>(Cl + (size_t)r1 * N + cc) =
                    __halves2half2(l0, l1);
            } else {
                *reinterpret_cast<float2*>(C + (size_t)r0 * N + cc) = v0;
                *reinterpret_cast<float2*>(C + (size_t)r1 * N + cc) = v1;
            }
        }
    }
}

// ---------------------------------------------------------------------------
// Batched weight pre-split: all 6 weights -> (hi, lo) fp16 pairs in 1 launch.
// Segment boundaries are the OFF_* constants (all multiples of 1024).
// ---------------------------------------------------------------------------
__global__ void wsplit_all_kernel(const float* __restrict__ w0,
                                  const float* __restrict__ w1,
                                  const float* __restrict__ w2,
                                  const float* __restrict__ w3,
                                  const float* __restrict__ w4,
                                  const float* __restrict__ w5,
                                  __half* __restrict__ wh,
                                  __half* __restrict__ wl)
{
    const long long i = ((long long)blockIdx.x * 256 + threadIdx.x) * 4;
    if (i >= WTOT) return;
    const float* src;
    long long base;
    if      (i < OFF_WOUT) { src = w0; base = OFF_QKV;  }
    else if (i < OFF_W1)   { src = w1; base = OFF_WOUT; }
    else if (i < OFF_W2)   { src = w2; base = OFF_W1;   }
    else if (i < OFF_W3)   { src = w3; base = OFF_W2;   }
    else if (i < OFF_W4)   { src = w4; base = OFF_W3;   }
    else                   { src = w5; base = OFF_W4;   }
    const float4 v = *reinterpret_cast<const float4*>(src + (i - base));
    __half h0, l0, h1, l1, h2, l2, h3, l3;
    h_split(v.x, h0, l0); h_split(v.y, h1, l1);
    h_split(v.z, h2, l2); h_split(v.w, h3, l3);
    *reinterpret_cast<__half2*>(wh + i)     = __halves2half2(h0, h1);
    *reinterpret_cast<__half2*>(wh + i + 2) = __halves2half2(h2, h3);
    *reinterpret_cast<__half2*>(wl + i)     = __halves2half2(l0, l1);
    *reinterpret_cast<__half2*>(wl + i + 2) = __halves2half2(l2, l3);
}

// ---------------------------------------------------------------------------
// fp32 SGEMM (fx-update: K=64). 128x128x8 tile.
// ---------------------------------------------------------------------------
template <bool BIAS, bool RES, bool GELU>
__global__ void sgemm_kernel(const float* __restrict__ A,
                             const float* __restrict__ Bm,
                             float* __restrict__ C,
                             const float* __restrict__ bias,
                             const float* __restrict__ res,
                             int M, int K, int N,
                             long long sA, long long sB, long long sC, long long sR)
{
    const int bz = blockIdx.z;
    A  += (long long)bz * sA;
    Bm += (long long)bz * sB;
    C  += (long long)bz * sC;
    if (RES) res += (long long)bz * sR;

    __shared__ float As[8][128];
    __shared__ float Bs[8][128];

    const int tid  = threadIdx.x;
    const int brow = blockIdx.y * 128;
    const int bcol = blockIdx.x * 128;
    const int tx = tid & 15;
    const int ty = tid >> 4;
    const int arow = tid >> 1;
    const int acol = (tid & 1) << 2;
    const int brw  = tid >> 5;
    const int bcl  = (tid & 31) << 2;

    float acc[8][8];
#pragma unroll
    for (int i = 0; i < 8; i++)
#pragma unroll
        for (int j = 0; j < 8; j++) acc[i][j] = 0.f;

    for (int k0 = 0; k0 < K; k0 += 8) {
        float4 av = *reinterpret_cast<const float4*>(
            &A[(long long)(brow + arow) * K + k0 + acol]);
        As[acol + 0][arow] = av.x;
        As[acol + 1][arow] = av.y;
        As[acol + 2][arow] = av.z;
        As[acol + 3][arow] = av.w;
        if (bcol + bcl + 3 < N) {
            *reinterpret_cast<float4*>(&Bs[brw][bcl]) =
                *reinterpret_cast<const float4*>(
                    &Bm[(long long)(k0 + brw) * N + bcol + bcl]);
        } else {
#pragma unroll
            for (int j = 0; j < 4; j++)
                Bs[brw][bcl + j] = (bcol + bcl + j < N)
                    ? Bm[(long long)(k0 + brw) * N + bcol + bcl + j] : 0.f;
        }
        __syncthreads();
#pragma unroll
        for (int k = 0; k < 8; k++) {
            float ar[8], br[8];
            *reinterpret_cast<float4*>(&ar[0]) = *reinterpret_cast<const float4*>(&As[k][ty * 8]);
            *reinterpret_cast<float4*>(&ar[4]) = *reinterpret_cast<const float4*>(&As[k][ty * 8 + 4]);
            *reinterpret_cast<float4*>(&br[0]) = *reinterpret_cast<const float4*>(&Bs[k][tx * 8]);
            *reinterpret_cast<float4*>(&br[4]) = *reinterpret_cast<const float4*>(&Bs[k][tx * 8 + 4]);
#pragma unroll
            for (int i = 0; i < 8; i++)
#pragma unroll
                for (int j = 0; j < 8; j++)
                    acc[i][j] += ar[i] * br[j];
        }
        __syncthreads();
    }
#pragma unroll
    for (int i = 0; i < 8; i++) {
        const long long r = brow + ty * 8 + i;
#pragma unroll
        for (int j = 0; j < 8; j++) {
            const int c = bcol + tx * 8 + j;
            if (c < N) {
                float v = acc[i][j];
                if (BIAS) v += bias[c];
                if (GELU) v = 0.5f * v * (1.f + erff(v * 0.70710678118654752f));
                if (RES)  v += res[r * N + c];
                C[r * N + c] = v;
            }
        }
    }
}

// ---------------------------------------------------------------------------
// Split-K fp32 GEMM for step 10 (N=64): C[128,64] += A-chunk @ B-chunk.
// grid (1, M/128, ksplit). C zeroed beforehand; bias omitted (BN-invariant).
// ---------------------------------------------------------------------------
__global__ void sgemm_nk_splitk_kernel(const float* __restrict__ A,
                                       const float* __restrict__ Bm,
                                       float* __restrict__ C,
                                       int M, int K, int N, int ksplit)
{
    __shared__ float As[8][128];
    __shared__ float Bs[8][64];

    const int tid  = threadIdx.x;
    const int brow = blockIdx.y * 128;
    const int kchunk = K / ksplit;
    const int kbeg = blockIdx.z * kchunk;
    const int kend = kbeg + kchunk;

    const int tx = tid & 15;
    const int ty = tid >> 4;
    const int arow = tid >> 1;
    const int acol = (tid & 1) << 2;
    const int brw  = tid >> 5;
    const int bcl  = (tid & 31) << 1;

    float acc[8][4];
#pragma unroll
    for (int i = 0; i < 8; i++)
#pragma unroll
        for (int j = 0; j < 4; j++) acc[i][j] = 0.f;

    for (int k0 = kbeg; k0 < kend; k0 += 8) {
        float4 av = *reinterpret_cast<const float4*>(
            &A[(long long)(brow + arow) * K + k0 + acol]);
        As[acol + 0][arow] = av.x;
        As[acol + 1][arow] = av.y;
        As[acol + 2][arow] = av.z;
        As[acol + 3][arow] = av.w;
        *reinterpret_cast<float2*>(&Bs[brw][bcl]) =
            *reinterpret_cast<const float2*>(&Bm[(long long)(k0 + brw) * N + bcl]);
        __syncthreads();
#pragma unroll
        for (int k = 0; k < 8; k++) {
            float ar[8], br[4];
            *reinterpret_cast<float4*>(&ar[0]) = *reinterpret_cast<const float4*>(&As[k][ty * 8]);
            *reinterpret_cast<float4*>(&ar[4]) = *reinterpret_cast<const float4*>(&As[k][ty * 8 + 4]);
            *reinterpret_cast<float4*>(&br[0]) = *reinterpret_cast<const float4*>(&Bs[k][tx * 4]);
#pragma unroll
            for (int i = 0; i < 8; i++)
#pragma unroll
                for (int j = 0; j < 4; j++)
                    acc[i][j] += ar[i] * br[j];
        }
        __syncthreads();
    }
#pragma unroll
    for (int i = 0; i < 8; i++) {
        const long long r = brow + ty * 8 + i;
#pragma unroll
        for (int j = 0; j < 4; j++)
            atomicAdd(&C[r * N + tx * 4 + j], acc[i][j]);
    }
}

// ---------------------------------------------------------------------------
// Split-K A^T B with atomic accumulation (C zeroed beforehand).
// ---------------------------------------------------------------------------
__global__ void atb_split_kernel(const float* __restrict__ A,
                                 const float* __restrict__ Bm,
                                 float* __restrict__ C,
                                 int K, int N, int lda, int ldb, int ldc,
                                 long long sA, long long sB, long long sC,
                                 float scale, int ksplit)
{
    const int bz = blockIdx.y;
    A  += (long long)bz * sA;
    Bm += (long long)bz * sB;
    C  += (long long)bz * sC;
    const int bcol = blockIdx.x * 64;
    const int kchunk = K / ksplit;
    const int kbeg = blockIdx.z * kchunk;
    const int kend = kbeg + kchunk;

    __shared__ float As[16][64];
    __shared__ float Bs[16][64];

    const int t  = threadIdx.x;
    const int kk = t >> 4;
    const int c4 = (t & 15) << 2;
    const int ty = t >> 4;
    const int tx = t & 15;

    float acc[4][4];
#pragma unroll
    for (int i = 0; i < 4; i++)
#pragma unroll
        for (int j = 0; j < 4; j++) acc[i][j] = 0.f;

    for (int k0 = kbeg; k0 < kend; k0 += 16) {
        *reinterpret_cast<float4*>(&As[kk][c4]) =
            *reinterpret_cast<const float4*>(&A[(long long)(k0 + kk) * lda + c4]);
        *reinterpret_cast<float4*>(&Bs[kk][c4]) =
            *reinterpret_cast<const float4*>(&Bm[(long long)(k0 + kk) * ldb + bcol + c4]);
        __syncthreads();
#pragma unroll
        for (int k = 0; k < 16; k++) {
            float ar[4], br[4];
            *reinterpret_cast<float4*>(ar) = *reinterpret_cast<const float4*>(&As[k][ty * 4]);
            *reinterpret_cast<float4*>(br) = *reinterpret_cast<const float4*>(&Bs[k][tx * 4]);
#pragma unroll
            for (int i = 0; i < 4; i++)
#pragma unroll
                for (int j = 0; j < 4; j++)
                    acc[i][j] += ar[i] * br[j];
        }
        __syncthreads();
    }
#pragma unroll
    for (int i = 0; i < 4; i++)
#pragma unroll
        for (int j = 0; j < 4; j++)
            atomicAdd(&C[(long long)(ty * 4 + i) * ldc + bcol + tx * 4 + j],
                      acc[i][j] * scale);
}

// ---------------------------------------------------------------------------
// attn apply: per (b,h): attn[n,:] = q[n,:] @ dots[b,h] -> split-fp16 output
// ---------------------------------------------------------------------------
__global__ void attn_kernel(const float* __restrict__ qkv,
                            const float* __restrict__ dots,
                            __half* __restrict__ outh,
                            __half* __restrict__ outl)
{
    const int bh = blockIdx.y;
    const int b  = bh >> 4;
    const int h  = bh & 15;
    const float* q = qkv + (long long)b * SEQ * (3 * HID) + h * DH;
    const float* D = dots + (long long)bh * DH * DH;
    const long long cbase = (long long)b * SEQ * HID + h * DH;
    const int row0 = blockIdx.x * 64;

    __shared__ float As[16][64];
    __shared__ float Bs[16][64];

    const int t   = threadIdx.x;
    const int ty  = t >> 4;
    const int tx  = t & 15;
    const int lm  = t >> 2;
    const int lk4 = (t & 3) << 2;
    const int bk  = t >> 4;
    const int bn4 = (t & 15) << 2;

    float acc[4][4];
#pragma unroll
    for (int i = 0; i < 4; i++)
#pragma unroll
        for (int j = 0; j < 4; j++) acc[i][j] = 0.f;

    for (int k0 = 0; k0 < DH; k0 += 16) {
        float4 av = *reinterpret_cast<const float4*>(
            &q[(long long)(row0 + lm) * (3 * HID) + k0 + lk4]);
        As[lk4 + 0][lm] = av.x;
        As[lk4 + 1][lm] = av.y;
        As[lk4 + 2][lm] = av.z;
        As[lk4 + 3][lm] = av.w;
        *reinterpret_cast<float4*>(&Bs[bk][bn4]) =
            *reinterpret_cast<const float4*>(&D[(k0 + bk) * DH + bn4]);
        __syncthreads();
#pragma unroll
        for (int k = 0; k < 16; k++) {
            float ar[4], br[4];
            *reinterpret_cast<float4*>(ar) = *reinterpret_cast<const float4*>(&As[k][ty * 4]);
            *reinterpret_cast<float4*>(br) = *reinterpret_cast<const float4*>(&Bs[k][tx * 4]);
#pragma unroll
            for (int i = 0; i < 4; i++)
#pragma unroll
                for (int j = 0; j < 4; j++)
                    acc[i][j] += ar[i] * br[j];
        }
        __syncthreads();
    }
#pragma unroll
    for (int i = 0; i < 4; i++)
#pragma unroll
        for (int j = 0; j < 4; j += 2) {
            const long long idx = cbase +
                (long long)(row0 + ty * 4 + i) * HID + tx * 4 + j;
            __half h0, l0, h1, l1;
            h_split(acc[i][j],     h0, l0);
            h_split(acc[i][j + 1], h1, l1);
            *reinterpret_cast<__half2*>(outh + idx) = __halves2half2(h0, h1);
            *reinterpret_cast<__half2*>(outl + idx) = __halves2half2(l0, l1);
        }
}

// ---------------------------------------------------------------------------
// Row LayerNorm over H=1024 with split-fp16 output
// ---------------------------------------------------------------------------
__global__ void ln_split_kernel(const float* __restrict__ x,
                                const float* __restrict__ g,
                                const float* __restrict__ b,
                                __half* __restrict__ yh,
                                __half* __restrict__ yl)
{
    const int row = blockIdx.x;
    const float4 v = reinterpret_cast<const float4*>(x + (long long)row * HID)[threadIdx.x];
    float s  = v.x + v.y + v.z + v.w;
    float sq = v.x * v.x + v.y * v.y + v.z * v.z + v.w * v.w;
#pragma unroll
    for (int o = 16; o; o >>= 1) {
        s  += __shfl_xor_sync(0xffffffffu, s,  o);
        sq += __shfl_xor_sync(0xffffffffu, sq, o);
    }
    __shared__ float ss[8], ssq[8];
    const int w = threadIdx.x >> 5, l = threadIdx.x & 31;
    if (l == 0) { ss[w] = s; ssq[w] = sq; }
    __syncthreads();
    if (w == 0) {
        s  = (l < 8) ? ss[l]  : 0.f;
        sq = (l < 8) ? ssq[l] : 0.f;
#pragma unroll
        for (int o = 4; o; o >>= 1) {
            s  += __shfl_xor_sync(0xffffffffu, s,  o);
            sq += __shfl_xor_sync(0xffffffffu, sq, o);
        }
        if (l == 0) { ss[0] = s; ssq[0] = sq; }
    }
    __syncthreads();
    const float mean = ss[0] * (1.f / HID);
    const float var  = ssq[0] * (1.f / HID) - mean * mean;
    const float rstd = rsqrtf(var + EPSV);
    const float4 gg = reinterpret_cast<const float4*>(g)[threadIdx.x];
    const float4 bb = reinterpret_cast<const float4*>(b)[threadIdx.x];
    float o0 = (v.x - mean) * rstd * gg.x + bb.x;
    float o1 = (v.y - mean) * rstd * gg.y + bb.y;
    float o2 = (v.z - mean) * rstd * gg.z + bb.z;
    float o3 = (v.w - mean) * rstd * gg.w + bb.w;
    __half h0, l0, h1, l1, h2, l2, h3, l3;
    h_split(o0, h0, l0); h_split(o1, h1, l1);
    h_split(o2, h2, l2); h_split(o3, h3, l3);
    const long long base = (long long)row * HID + threadIdx.x * 4;
    *reinterpret_cast<__half2*>(yh + base)     = __halves2half2(h0, h1);
    *reinterpret_cast<__half2*>(yh + base + 2) = __halves2half2(h2, h3);
    *reinterpret_cast<__half2*>(yl + base)     = __halves2half2(l0, l1);
    *reinterpret_cast<__half2*>(yl + base + 2) = __halves2half2(l2, l3);
}

// ---------------------------------------------------------------------------
// k/v LayerNorm over DH=64 per (token, head) -> [b][h][n][d] layout
// ---------------------------------------------------------------------------
__global__ void kvln_kernel(const float* __restrict__ qkv,
                            const float* __restrict__ kg, const float* __restrict__ kb,
                            const float* __restrict__ vg, const float* __restrict__ vb,
                            float* __restrict__ kn, float* __restrict__ vn)
{
    const long long r = (long long)blockIdx.x * 8 + (threadIdx.x >> 5);
    const int lane = threadIdx.x & 31;
    const int bh = (int)(r >> 12);
    const int n  = (int)(r & 4095);
    const int b  = bh >> 4;
    const int h  = bh & 15;
    const float* base = qkv + ((long long)(b * SEQ + n)) * (3 * HID) + h * DH;
    const float2 kv = *reinterpret_cast<const float2*>(base + HID     + lane * 2);
    const float2 vv = *reinterpret_cast<const float2*>(base + 2 * HID + lane * 2);
    float s1 = kv.x + kv.y, q1 = kv.x * kv.x + kv.y * kv.y;
    float s2 = vv.x + vv.y, q2 = vv.x * vv.x + vv.y * vv.y;
#pragma unroll
    for (int o = 16; o; o >>= 1) {
        s1 += __shfl_xor_sync(0xffffffffu, s1, o);
        q1 += __shfl_xor_sync(0xffffffffu, q1, o);
        s2 += __shfl_xor_sync(0xffffffffu, s2, o);
        q2 += __shfl_xor_sync(0xffffffffu, q2, o);
    }
    const float m1 = s1 * (1.f / DH), rs1 = rsqrtf(q1 * (1.f / DH) - m1 * m1 + EPSV);
    const float m2 = s2 * (1.f / DH), rs2 = rsqrtf(q2 * (1.f / DH) - m2 * m2 + EPSV);
    const int d = lane * 2;
    float2 ko, vo;
    ko.x = (kv.x - m1) * rs1 * kg[d]     + kb[d];
    ko.y = (kv.y - m1) * rs1 * kg[d + 1] + kb[d + 1];
    vo.x = (vv.x - m2) * rs2 * vg[d]     + vb[d];
    vo.y = (vv.y - m2) * rs2 * vg[d + 1] + vb[d + 1];
    *reinterpret_cast<float2*>(kn + r * DH + d) = ko;
    *reinterpret_cast<float2*>(vn + r * DH + d) = vo;
}

// ---------------------------------------------------------------------------
// BatchNorm1d (training stats): two-stage (atomic partials, finalize)
// ---------------------------------------------------------------------------
__global__ void bn_stats1_kernel(const float* __restrict__ xp, float* __restrict__ psum)
{
    const int p = blockIdx.x;           // channel
    const int seg = blockIdx.y;         // row segment (8 segs x 2048 rows)
    const int r0 = seg * (MROWS / 8);
    float s = 0.f, sq = 0.f;
    for (int r = r0 + threadIdx.x; r < r0 + MROWS / 8; r += 256) {
        const float v = xp[(long long)r * PSI + p];
        s += v; sq += v * v;
    }
#pragma unroll
    for (int o = 16; o; o >>= 1) {
        s  += __shfl_xor_sync(0xffffffffu, s,  o);
        sq += __shfl_xor_sync(0xffffffffu, sq, o);
    }
    __shared__ float ss[8], ssq[8];
    const int w = threadIdx.x >> 5, l = threadIdx.x & 31;
    if (l == 0) { ss[w] = s; ssq[w] = sq; }
    __syncthreads();
    if (threadIdx.x == 0) {
        float ts = 0.f, tq = 0.f;
        for (int i = 0; i < 8; i++) { ts += ss[i]; tq += ssq[i]; }
        atomicAdd(&psum[p], ts);
        atomicAdd(&psum[PSI + p], tq);
    }
}

__global__ void bn_stats2_kernel(const float* __restrict__ psum, float* __restrict__ stats)
{
    const int p = threadIdx.x;          // 64 threads
    const float mean = psum[p] * (1.f / MROWS);
    const float var  = psum[PSI + p] * (1.f / MROWS) - mean * mean;
    stats[p]       = mean;
    stats[PSI + p] = rsqrtf(var + EPSV);
}

__global__ void bn_apply_kernel(const float* __restrict__ xp,
                                const float* __restrict__ stats,
                                const float* __restrict__ bng,
                                const float* __restrict__ bnb,
                                const float* __restrict__ mu,
                                float* __restrict__ xn,
                                float* __restrict__ xs)
{
    const long long i = (long long)blockIdx.x * 256 + threadIdx.x;
    const int p = (int)(i & (PSI - 1));
    const float v = (xp[i] - stats[p]) * stats[PSI + p] * bng[p] + bnb[p];
    xn[i] = v;
    const float m = mu[p];
    const float sp = (m > 20.f) ? m : log1pf(expf(m));
    xs[i] = v * sp;
}

// ---------------------------------------------------------------------------
// Launch
// ---------------------------------------------------------------------------
extern "C" void kernel_launch(void* const* d_in, const int* in_sizes, int n_in,
                              void* d_out, int out_size)
{
    const float* x    = (const float*)d_in[0];
    const float* fx   = (const float*)d_in[1];
    const float* mu   = (const float*)d_in[2];
    const float* ln1g = (const float*)d_in[3];
    const float* ln1b = (const float*)d_in[4];
    const float* Wqkv = (const float*)d_in[5];
    const float* kg   = (const float*)d_in[6];
    const float* kb   = (const float*)d_in[7];
    const float* vg   = (const float*)d_in[8];
    const float* vb   = (const float*)d_in[9];
    const float* Wout = (const float*)d_in[10];
    const float* bout = (const float*)d_in[11];
    const float* ln2g = (const float*)d_in[12];
    const float* ln2b = (const float*)d_in[13];
    const float* W1   = (const float*)d_in[14];
    const float* b1   = (const float*)d_in[15];
    const float* W2   = (const float*)d_in[16];
    const float* b2   = (const float*)d_in[17];
    const float* Wp   = (const float*)d_in[18];
    const float* bp   = (const float*)d_in[19];  // BN-invariant; unused
    const float* bng  = (const float*)d_in[20];
    const float* bnb  = (const float*)d_in[21];
    const float* ln3g = (const float*)d_in[22];
    const float* ln3b = (const float*)d_in[23];
    const float* W3   = (const float*)d_in[24];
    const float* b3   = (const float*)d_in[25];
    const float* W4   = (const float*)d_in[26];
    const float* b4   = (const float*)d_in[27];
    (void)bp;

    float* outx  = (float*)d_out;
    float* outfx = outx + (long long)MROWS * HID;

    float *p_qkv, *p_kn, *p_vn, *p_dots, *p_x1;
    float *p_xp, *p_xn, *p_xs, *p_stats, *p_psum, *p_kern, *p_fx1;
    __half *p_wh, *p_wl, *p_lnh, *p_lnl, *p_atth, *p_attl, *p_midh, *p_midl;
    cudaGetSymbolAddress((void**)&p_qkv,  g_qkv);
    cudaGetSymbolAddress((void**)&p_kn,   g_kn);
    cudaGetSymbolAddress((void**)&p_vn,   g_vn);
    cudaGetSymbolAddress((void**)&p_dots, g_dots);
    cudaGetSymbolAddress((void**)&p_x1,   g_x1);
    cudaGetSymbolAddress((void**)&p_xp,   g_xp);
    cudaGetSymbolAddress((void**)&p_xn,   g_xn);
    cudaGetSymbolAddress((void**)&p_xs,   g_xs);
    cudaGetSymbolAddress((void**)&p_stats,g_stats);
    cudaGetSymbolAddress((void**)&p_psum, g_psum);
    cudaGetSymbolAddress((void**)&p_kern, g_kern);
    cudaGetSymbolAddress((void**)&p_fx1,  g_fx1);
    cudaGetSymbolAddress((void**)&p_wh,   g_wh);
    cudaGetSymbolAddress((void**)&p_wl,   g_wl);
    cudaGetSymbolAddress((void**)&p_lnh,  g_lnh);
    cudaGetSymbolAddress((void**)&p_lnl,  g_lnl);
    cudaGetSymbolAddress((void**)&p_atth, g_atth);
    cudaGetSymbolAddress((void**)&p_attl, g_attl);
    cudaGetSymbolAddress((void**)&p_midh, g_midh);
    cudaGetSymbolAddress((void**)&p_midl, g_midl);

    cudaFuncSetAttribute(h16_gemm_kernel<false, false, false, false>,
                         cudaFuncAttributeMaxDynamicSharedMemorySize, H16_SMEM_BYTES);
    cudaFuncSetAttribute(h16_gemm_kernel<true, true, false, false>,
                         cudaFuncAttributeMaxDynamicSharedMemorySize, H16_SMEM_BYTES);
    cudaFuncSetAttribute(h16_gemm_kernel<true, false, true, true>,
                         cudaFuncAttributeMaxDynamicSharedMemorySize, H16_SMEM_BYTES);
    cudaFuncSetAttribute(h16_gemm_kernel<true, false, false, false>,
                         cudaFuncAttributeMaxDynamicSharedMemorySize, H16_SMEM_BYTES);

    // 0) pre-split all weights to fp16 pairs (single batched launch)
    wsplit_all_kernel<<<WTOT / 1024, 256>>>(Wqkv, Wout, W1, W2, W3, W4, p_wh, p_wl);

    // 1) h = LN1(x) -> split
    ln_split_kernel<<<MROWS, 256>>>(x, ln1g, ln1b, p_lnh, p_lnl);
    // 2) qkv = h @ Wqkv
    h16_gemm_kernel<false, false, false, false><<<dim3(24, 128), 256, H16_SMEM_BYTES>>>(
        p_lnh, p_lnl, p_wh + OFF_QKV, p_wl + OFF_QKV,
        p_qkv, nullptr, nullptr, nullptr, nullptr, MROWS, HID, 3 * HID);
    // 3) LN(k), LN(v)
    kvln_kernel<<<(Bq * NHEAD * SEQ) / 8, 256>>>(p_qkv, kg, kb, vg, vb, p_kn, p_vn);
    // 4) dots = k^T v / N
    cudaMemsetAsync(p_dots, 0, sizeof(float) * Bq * NHEAD * DH * DH);
    atb_split_kernel<<<dim3(1, Bq * NHEAD, 16), 256>>>(
        p_kn, p_vn, p_dots, SEQ, DH, DH, DH, DH,
        (long long)SEQ * DH, (long long)SEQ * DH, (long long)DH * DH,
        1.f / (float)SEQ, 16);
    // 5) attn = q @ dots -> split
    attn_kernel<<<dim3(SEQ / 64, Bq * NHEAD), 256>>>(p_qkv, p_dots, p_atth, p_attl);
    // 6) x1 = attn @ Wout + bout + x
    h16_gemm_kernel<true, true, false, false><<<dim3(8, 128), 256, H16_SMEM_BYTES>>>(
        p_atth, p_attl, p_wh + OFF_WOUT, p_wl + OFF_WOUT,
        p_x1, nullptr, nullptr, bout, x, MROWS, HID, HID);
    // 7) h = LN2(x1) -> split
    ln_split_kernel<<<MROWS, 256>>>(p_x1, ln2g, ln2b, p_lnh, p_lnl);
    // 8) mid = gelu(h @ W1 + b1) -> split
    h16_gemm_kernel<true, false, true, true><<<dim3(32, 128), 256, H16_SMEM_BYTES>>>(
        p_lnh, p_lnl, p_wh + OFF_W1, p_wl + OFF_W1,
        nullptr, p_midh, p_midl, b1, nullptr, MROWS, HID, 4 * HID);
    // 9) x_out = mid @ W2 + b2 + x1 -> d_out first half
    h16_gemm_kernel<true, true, false, false><<<dim3(8, 128), 256, H16_SMEM_BYTES>>>(
        p_midh, p_midl, p_wh + OFF_W2, p_wl + OFF_W2,
        outx, nullptr, nullptr, b2, p_x1, MROWS, 4 * HID, HID);
    // 10) xp = x_out @ Wp (bias bp cancels in BN) -- split-K x8, atomics
    cudaMemsetAsync(p_xp, 0, sizeof(float) * MROWS * PSI);
    sgemm_nk_splitk_kernel<<<dim3(1, MROWS / 128, 8), 256>>>(
        outx, Wp, p_xp, MROWS, HID, PSI, 8);
    // 11-12) BatchNorm (two-stage stats) + softplus scaling
    cudaMemsetAsync(p_psum, 0, sizeof(float) * 2 * PSI);
    bn_stats1_kernel<<<dim3(PSI, 8), 256>>>(p_xp, p_psum);
    bn_stats2_kernel<<<1, PSI>>>(p_psum, p_stats);
    bn_apply_kernel<<<(MROWS * PSI) / 256, 256>>>(p_xp, p_stats, bng, bnb, mu, p_xn, p_xs);
    // 13) kern = x_^T @ fx per batch
    cudaMemsetAsync(p_kern, 0, sizeof(float) * Bq * PSI * HID);
    atb_split_kernel<<<dim3(HID / 64, Bq, 16), 256>>>(
        p_xn, fx, p_kern, SEQ, HID, PSI, HID, HID,
        (long long)SEQ * PSI, (long long)SEQ * HID, (long long)PSI * HID, 1.f, 16);
    // 14) fx1 = (x_ * sp(mu)) @ kern + fx per batch (fp32, K=64)
    sgemm_kernel<false, true, false><<<dim3(8, 32, Bq), 256>>>(
        p_xs, p_kern, p_fx1, nullptr, fx, SEQ, PSI, HID,
        (long long)SEQ * PSI, (long long)PSI * HID,
        (long long)SEQ * HID, (long long)SEQ * HID);
    // 15) h = LN3(fx1) -> split
    ln_split_kernel<<<MROWS, 256>>>(p_fx1, ln3g, ln3b, p_lnh, p_lnl);
    // 16) mid = gelu(h @ W3 + b3) -> split
    h16_gemm_kernel<true, false, true, true><<<dim3(32, 128), 256, H16_SMEM_BYTES>>>(
        p_lnh, p_lnl, p_wh + OFF_W3, p_wl + OFF_W3,
        nullptr, p_midh, p_midl, b3, nullptr, MROWS, HID, 4 * HID);
    // 17) fx_out = mid @ W4 + b4 -> d_out second half
    h16_gemm_kernel<true, false, false, false><<<dim3(8, 128), 256, H16_SMEM_BYTES>>>(
        p_midh, p_midl, p_wh + OFF_W4, p_wl + OFF_W4,
        outfx, nullptr, nullptr, b4, nullptr, MROWS, 4 * HID, HID);
}

// round 17
// speedup vs baseline: 1.1082x; 1.0059x over previous
#include <cuda_runtime.h>
#include <cuda_fp16.h>
#include <math.h>
#include <stdint.h>

// ---------------------------------------------------------------------------
// Problem constants: B=4, N=4096, H=1024, HEADS=16, DH=64, PSI=64, M=B*N=16384
// ---------------------------------------------------------------------------
#define Bq    4
#define SEQ   4096
#define HID   1024
#define NHEAD 16
#define DH    64
#define PSI   64
#define MROWS (Bq * SEQ)
#define EPSV  1e-5f

// Weight offsets in the packed split-weight buffers (element counts)
#define OFF_QKV  0
#define OFF_WOUT 3145728
#define OFF_W1   4194304
#define OFF_W2   8388608
#define OFF_W3   12582912
#define OFF_W4   16777216
#define WTOT     20971520

// ---------------------------------------------------------------------------
// Static device scratch
// ---------------------------------------------------------------------------
__device__ float  g_qkv [MROWS * 3 * HID];
__device__ float  g_dots[Bq * NHEAD * DH * DH];
__device__ float  g_x1  [MROWS * HID];
__device__ float  g_xp  [MROWS * PSI];
__device__ float  g_xn  [MROWS * PSI];
__device__ float  g_xs  [MROWS * PSI];
__device__ float  g_stats[2 * PSI];
__device__ float  g_psum [2 * PSI];
__device__ float  g_kern[Bq * PSI * HID];
__device__ float  g_fx1 [MROWS * HID];
// split-fp16 operand buffers
__device__ __half g_wh  [WTOT];
__device__ __half g_wl  [WTOT];
__device__ __half g_lnh [MROWS * HID];
__device__ __half g_lnl [MROWS * HID];
__device__ __half g_atth[MROWS * HID];
__device__ __half g_attl[MROWS * HID];
__device__ __half g_midh[MROWS * 4 * HID];
__device__ __half g_midl[MROWS * 4 * HID];

// ---------------------------------------------------------------------------
// PTX helpers
// ---------------------------------------------------------------------------
__device__ __forceinline__ void cp_async16(uint32_t dst, const void* src) {
    asm volatile("cp.async.cg.shared.global [%0], [%1], 16;"
                 :: "r"(dst), "l"(src));
}
#define CP_COMMIT()  asm volatile("cp.async.commit_group;")
#define CP_WAIT(n)   asm volatile("cp.async.wait_group %0;" :: "n"(n))

__device__ __forceinline__ void ldm_x4(uint32_t* r, uint32_t addr) {
    asm volatile("ldmatrix.sync.aligned.m8n8.x4.shared.b16 {%0,%1,%2,%3}, [%4];"
                 : "=r"(r[0]), "=r"(r[1]), "=r"(r[2]), "=r"(r[3]) : "r"(addr));
}
__device__ __forceinline__ void ldm_x4_t(uint32_t* r, uint32_t addr) {
    asm volatile("ldmatrix.sync.aligned.m8n8.x4.trans.shared.b16 {%0,%1,%2,%3}, [%4];"
                 : "=r"(r[0]), "=r"(r[1]), "=r"(r[2]), "=r"(r[3]) : "r"(addr));
}
#define MMA_F16(c0,c1,c2,c3,a0,a1,a2,a3,b0,b1)                              \
    asm volatile("mma.sync.aligned.m16n8k16.row.col.f32.f16.f16.f32 "       \
                 "{%0,%1,%2,%3}, {%4,%5,%6,%7}, {%8,%9}, {%0,%1,%2,%3};"    \
                 : "+f"(c0), "+f"(c1), "+f"(c2), "+f"(c3)                   \
                 : "r"(a0), "r"(a1), "r"(a2), "r"(a3), "r"(b0), "r"(b1))

// fp16 Dekker split: v ~= hi + lo (pair carries ~22 mantissa bits)
__device__ __forceinline__ void h_split(float v, __half& hi, __half& lo) {
    const __half h = __float2half_rn(v);
    hi = h;
    lo = __float2half_rn(v - __half2float(h));
}

// ---------------------------------------------------------------------------
// Split-fp16 GEMM (winning config): C = (Ah+Al) @ (Bh+Bl) (+bias)(+gelu)
// (+res). acc += Ah*Bh + Al*Bh + Ah*Bl. Tile 128x128x32, 256 threads
// (2x4 warps, warp 64x32), 2-stage cp.async, 2 CTAs/SM.
// M%128==0, N%128==0, K%32==0.
// ---------------------------------------------------------------------------
#define ASTR 40                          // halves per A row (32 + 8 pad)
#define BSTR 136                         // halves per B row (128 + 8 pad)
#define A_SZ (128 * ASTR)                // 5120 halves
#define B_SZ (32 * BSTR)                 // 4352 halves
#define STG  (2 * A_SZ + 2 * B_SZ)       // 18944 halves per stage
#define H16_SMEM_BYTES (2 * STG * 2)     // 75776 bytes -> 2 CTAs/SM

template <bool BIAS, bool RES, bool GELU, bool SPLITOUT>
__global__ void __launch_bounds__(256, 2) h16_gemm_kernel(
    const __half* __restrict__ Ah, const __half* __restrict__ Al,
    const __half* __restrict__ Bh, const __half* __restrict__ Bl,
    float* __restrict__ C, __half* __restrict__ Ch, __half* __restrict__ Cl,
    const float* __restrict__ bias, const float* __restrict__ res,
    int M, int K, int N)
{
    extern __shared__ __half hsm[];
    const uint32_t smb = (uint32_t)__cvta_generic_to_shared(hsm);

    const int tid  = threadIdx.x;
    const int w    = tid >> 5;
    const int lane = tid & 31;
    const int grp  = lane >> 2;
    const int qd   = lane & 3;
    const int wm   = w >> 2;             // 0..1
    const int wn   = w & 3;              // 0..3
    const int mb   = wm * 64;
    const int nb   = wn * 32;

    const int bm = blockIdx.y * 128;
    const int bn = blockIdx.x * 128;

    float acc[4][4][4];
#pragma unroll
    for (int mi = 0; mi < 4; mi++)
#pragma unroll
        for (int ni = 0; ni < 4; ni++)
#pragma unroll
            for (int r = 0; r < 4; r++) acc[mi][ni][r] = 0.f;

    const int chunks = K >> 5;

    auto load_stage = [&](int c, int s) {
        const int k0 = c << 5;
        const uint32_t sb = smb + (uint32_t)(s * STG * 2);
        // A: 512 hi + 512 lo 16B-chunks (row = tt>>2, chunk = tt&3)
#pragma unroll
        for (int i = 0; i < 4; i++) {
            const int t  = tid + (i << 8);
            const int tt = t & 511;
            const int row = tt >> 2, ch = tt & 3;
            const __half* src = (t < 512) ? Ah : Al;
            const uint32_t off = (t < 512) ? 0u : (uint32_t)A_SZ;
            cp_async16(sb + (off + row * ASTR + ch * 8) * 2,
                       src + (size_t)(bm + row) * K + k0 + ch * 8);
        }
        // B: 512 hi + 512 lo 16B-chunks (k row = tt>>4, chunk = tt&15)
#pragma unroll
        for (int i = 4; i < 8; i++) {
            const int t  = tid + (i << 8);
            const int tt = t & 511;
            const int kr = tt >> 4, ch = tt & 15;
            const __half* src = (t < 1536) ? Bh : Bl;
            const uint32_t off = (t < 1536) ? (uint32_t)(2 * A_SZ)
                                            : (uint32_t)(2 * A_SZ + B_SZ);
            cp_async16(sb + (off + kr * BSTR + ch * 8) * 2,
                       src + (size_t)(k0 + kr) * N + bn + ch * 8);
        }
    };

    load_stage(0, 0);
    CP_COMMIT();

    // lane-specific ldmatrix addressing
    const int arow = lane & 15;
    const int ahk  = (lane >> 4) << 3;                   // A k offset 0/8
    const int bkr  = ((lane >> 3) & 1) * 8 + (lane & 7); // B k row
    const int bno  = (lane >> 4) << 3;                   // B n offset 0/8

    for (int c = 0; c < chunks; ++c) {
        const int s = c & 1;
        if (c + 1 < chunks) {
            load_stage(c + 1, s ^ 1);
            CP_COMMIT();
            CP_WAIT(1);
        } else {
            CP_WAIT(0);
        }
        __syncthreads();

        const uint32_t sb  = smb + (uint32_t)(s * STG * 2);
        const uint32_t sAh = sb;
        const uint32_t sBh = sb + (uint32_t)(2 * A_SZ * 2);
#pragma unroll
        for (int ks = 0; ks < 2; ks++) {
            const int kb = ks << 4;
            uint32_t a_h[4][4], a_l[4][4];
#pragma unroll
            for (int mi = 0; mi < 4; mi++) {
                const uint32_t ad = sAh +
                    (uint32_t)(((mb + mi * 16 + arow) * ASTR + kb + ahk) * 2);
                ldm_x4(a_h[mi], ad);
                ldm_x4(a_l[mi], ad + (uint32_t)(A_SZ * 2));
            }
            uint32_t b_h[2][4], b_l[2][4];
#pragma unroll
            for (int nj = 0; nj < 2; nj++) {
                const uint32_t bd = sBh +
                    (uint32_t)(((kb + bkr) * BSTR + nb + nj * 16 + bno) * 2);
                ldm_x4_t(b_h[nj], bd);
                ldm_x4_t(b_l[nj], bd + (uint32_t)(B_SZ * 2));
            }
#pragma unroll
            for (int mi = 0; mi < 4; mi++)
#pragma unroll
                for (int ni = 0; ni < 4; ni++) {
                    const int nj = ni >> 1;
                    const int bi = (ni & 1) << 1;
                    MMA_F16(acc[mi][ni][0], acc[mi][ni][1],
                            acc[mi][ni][2], acc[mi][ni][3],
                            a_h[mi][0], a_h[mi][1], a_h[mi][2], a_h[mi][3],
                            b_h[nj][bi], b_h[nj][bi + 1]);
                    MMA_F16(acc[mi][ni][0], acc[mi][ni][1],
                            acc[mi][ni][2], acc[mi][ni][3],
                            a_l[mi][0], a_l[mi][1], a_l[mi][2], a_l[mi][3],
                            b_h[nj][bi], b_h[nj][bi + 1]);
                    MMA_F16(acc[mi][ni][0], acc[mi][ni][1],
                            acc[mi][ni][2], acc[mi][ni][3],
                            a_h[mi][0], a_h[mi][1], a_h[mi][2], a_h[mi][3],
                            b_l[nj][bi], b_l[nj][bi + 1]);
                }
        }
        __syncthreads();
    }

    // epilogue
#pragma unroll
    for (int mi = 0; mi < 4; mi++) {
        const int r0 = bm + mb + mi * 16 + grp;
        const int r1 = r0 + 8;
#pragma unroll
        for (int ni = 0; ni < 4; ni++) {
            const int cc = bn + nb + ni * 8 + qd * 2;
            float2 v0 = make_float2(acc[mi][ni][0], acc[mi][ni][1]);
            float2 v1 = make_float2(acc[mi][ni][2], acc[mi][ni][3]);
            if (BIAS) {
                const float2 bb = *reinterpret_cast<const float2*>(bias + cc);
                v0.x += bb.x; v0.y += bb.y; v1.x += bb.x; v1.y += bb.y;
            }
            if (GELU) {
                v0.x = 0.5f * v0.x * (1.f + erff(v0.x * 0.70710678118654752f));
                v0.y = 0.5f * v0.y * (1.f + erff(v0.y * 0.70710678118654752f));
                v1.x = 0.5f * v1.x * (1.f + erff(v1.x * 0.70710678118654752f));
                v1.y = 0.5f * v1.y * (1.f + erff(v1.y * 0.70710678118654752f));
            }
            if (RES) {
                const float2 ra = *reinterpret_cast<const float2*>(
                    res + (size_t)r0 * N + cc);
                const float2 rb = *reinterpret_cast<const float2*>(
                    res + (size_t)r1 * N + cc);
                v0.x += ra.x; v0.y += ra.y; v1.x += rb.x; v1.y += rb.y;
            }
            if (SPLITOUT) {
                __half h0, l0, h1, l1;
                h_split(v0.x, h0, l0); h_split(v0.y, h1, l1);
                *reinterpret_cast<__half2*>(Ch + (size_t)r0 * N + cc) =
                    __halves2half2(h0, h1);
                *reinterpret_cast<__half2*>(Cl + (size_t)r0 * N + cc) =
                    __halves2half2(l0, l1);
                h_split(v1.x, h0, l0); h_split(v1.y, h1, l1);
                *reinterpret_cast<__half2*>(Ch + (size_t)r1 * N + cc) =
                    __halves2half2(h0, h1);
                *reinterpret_cast<__half2*>(Cl + (size_t)r1 * N + cc) =
                    __halves2half2(l0, l1);
            } else {
                *reinterpret_cast<float2*>(C + (size_t)r0 * N + cc) = v0;
                *reinterpret_cast<float2*>(C + (size_t)r1 * N + cc) = v1;
            }
        }
    }
}

// ---------------------------------------------------------------------------
// Batched weight pre-split: all 6 weights -> (hi, lo) fp16 pairs in 1 launch.
// ---------------------------------------------------------------------------
__global__ void wsplit_all_kernel(const float* __restrict__ w0,
                                  const float* __restrict__ w1,
                                  const float* __restrict__ w2,
                                  const float* __restrict__ w3,
                                  const float* __restrict__ w4,
                                  const float* __restrict__ w5,
                                  __half* __restrict__ wh,
                                  __half* __restrict__ wl)
{
    const long long i = ((long long)blockIdx.x * 256 + threadIdx.x) * 4;
    if (i >= WTOT) return;
    const float* src;
    long long base;
    if      (i < OFF_WOUT) { src = w0; base = OFF_QKV;  }
    else if (i < OFF_W1)   { src = w1; base = OFF_WOUT; }
    else if (i < OFF_W2)   { src = w2; base = OFF_W1;   }
    else if (i < OFF_W3)   { src = w3; base = OFF_W2;   }
    else if (i < OFF_W4)   { src = w4; base = OFF_W3;   }
    else                   { src = w5; base = OFF_W4;   }
    const float4 v = *reinterpret_cast<const float4*>(src + (i - base));
    __half h0, l0, h1, l1, h2, l2, h3, l3;
    h_split(v.x, h0, l0); h_split(v.y, h1, l1);
    h_split(v.z, h2, l2); h_split(v.w, h3, l3);
    *reinterpret_cast<__half2*>(wh + i)     = __halves2half2(h0, h1);
    *reinterpret_cast<__half2*>(wh + i + 2) = __halves2half2(h2, h3);
    *reinterpret_cast<__half2*>(wl + i)     = __halves2half2(l0, l1);
    *reinterpret_cast<__half2*>(wl + i + 2) = __halves2half2(l2, l3);
}

// ---------------------------------------------------------------------------
// fp32 SGEMM (fx-update: K=64). 128x128x8 tile.
// ---------------------------------------------------------------------------
template <bool BIAS, bool RES, bool GELU>
__global__ void sgemm_kernel(const float* __restrict__ A,
                             const float* __restrict__ Bm,
                             float* __restrict__ C,
                             const float* __restrict__ bias,
                             const float* __restrict__ res,
                             int M, int K, int N,
                             long long sA, long long sB, long long sC, long long sR)
{
    const int bz = blockIdx.z;
    A  += (long long)bz * sA;
    Bm += (long long)bz * sB;
    C  += (long long)bz * sC;
    if (RES) res += (long long)bz * sR;

    __shared__ float As[8][128];
    __shared__ float Bs[8][128];

    const int tid  = threadIdx.x;
    const int brow = blockIdx.y * 128;
    const int bcol = blockIdx.x * 128;
    const int tx = tid & 15;
    const int ty = tid >> 4;
    const int arow = tid >> 1;
    const int acol = (tid & 1) << 2;
    const int brw  = tid >> 5;
    const int bcl  = (tid & 31) << 2;

    float acc[8][8];
#pragma unroll
    for (int i = 0; i < 8; i++)
#pragma unroll
        for (int j = 0; j < 8; j++) acc[i][j] = 0.f;

    for (int k0 = 0; k0 < K; k0 += 8) {
        float4 av = *reinterpret_cast<const float4*>(
            &A[(long long)(brow + arow) * K + k0 + acol]);
        As[acol + 0][arow] = av.x;
        As[acol + 1][arow] = av.y;
        As[acol + 2][arow] = av.z;
        As[acol + 3][arow] = av.w;
        if (bcol + bcl + 3 < N) {
            *reinterpret_cast<float4*>(&Bs[brw][bcl]) =
                *reinterpret_cast<const float4*>(
                    &Bm[(long long)(k0 + brw) * N + bcol + bcl]);
        } else {
#pragma unroll
            for (int j = 0; j < 4; j++)
                Bs[brw][bcl + j] = (bcol + bcl + j < N)
                    ? Bm[(long long)(k0 + brw) * N + bcol + bcl + j] : 0.f;
        }
        __syncthreads();
#pragma unroll
        for (int k = 0; k < 8; k++) {
            float ar[8], br[8];
            *reinterpret_cast<float4*>(&ar[0]) = *reinterpret_cast<const float4*>(&As[k][ty * 8]);
            *reinterpret_cast<float4*>(&ar[4]) = *reinterpret_cast<const float4*>(&As[k][ty * 8 + 4]);
            *reinterpret_cast<float4*>(&br[0]) = *reinterpret_cast<const float4*>(&Bs[k][tx * 8]);
            *reinterpret_cast<float4*>(&br[4]) = *reinterpret_cast<const float4*>(&Bs[k][tx * 8 + 4]);
#pragma unroll
            for (int i = 0; i < 8; i++)
#pragma unroll
                for (int j = 0; j < 8; j++)
                    acc[i][j] += ar[i] * br[j];
        }
        __syncthreads();
    }
#pragma unroll
    for (int i = 0; i < 8; i++) {
        const long long r = brow + ty * 8 + i;
#pragma unroll
        for (int j = 0; j < 8; j++) {
            const int c = bcol + tx * 8 + j;
            if (c < N) {
                float v = acc[i][j];
                if (BIAS) v += bias[c];
                if (GELU) v = 0.5f * v * (1.f + erff(v * 0.70710678118654752f));
                if (RES)  v += res[r * N + c];
                C[r * N + c] = v;
            }
        }
    }
}

// ---------------------------------------------------------------------------
// Split-K fp32 GEMM for step 10 (N=64): C[128,64] += A-chunk @ B-chunk.
// ---------------------------------------------------------------------------
__global__ void sgemm_nk_splitk_kernel(const float* __restrict__ A,
                                       const float* __restrict__ Bm,
                                       float* __restrict__ C,
                                       int M, int K, int N, int ksplit)
{
    __shared__ float As[8][128];
    __shared__ float Bs[8][64];

    const int tid  = threadIdx.x;
    const int brow = blockIdx.y * 128;
    const int kchunk = K / ksplit;
    const int kbeg = blockIdx.z * kchunk;
    const int kend = kbeg + kchunk;

    const int tx = tid & 15;
    const int ty = tid >> 4;
    const int arow = tid >> 1;
    const int acol = (tid & 1) << 2;
    const int brw  = tid >> 5;
    const int bcl  = (tid & 31) << 1;

    float acc[8][4];
#pragma unroll
    for (int i = 0; i < 8; i++)
#pragma unroll
        for (int j = 0; j < 4; j++) acc[i][j] = 0.f;

    for (int k0 = kbeg; k0 < kend; k0 += 8) {
        float4 av = *reinterpret_cast<const float4*>(
            &A[(long long)(brow + arow) * K + k0 + acol]);
        As[acol + 0][arow] = av.x;
        As[acol + 1][arow] = av.y;
        As[acol + 2][arow] = av.z;
        As[acol + 3][arow] = av.w;
        *reinterpret_cast<float2*>(&Bs[brw][bcl]) =
            *reinterpret_cast<const float2*>(&Bm[(long long)(k0 + brw) * N + bcl]);
        __syncthreads();
#pragma unroll
        for (int k = 0; k < 8; k++) {
            float ar[8], br[4];
            *reinterpret_cast<float4*>(&ar[0]) = *reinterpret_cast<const float4*>(&As[k][ty * 8]);
            *reinterpret_cast<float4*>(&ar[4]) = *reinterpret_cast<const float4*>(&As[k][ty * 8 + 4]);
            *reinterpret_cast<float4*>(&br[0]) = *reinterpret_cast<const float4*>(&Bs[k][tx * 4]);
#pragma unroll
            for (int i = 0; i < 8; i++)
#pragma unroll
                for (int j = 0; j < 4; j++)
                    acc[i][j] += ar[i] * br[j];
        }
        __syncthreads();
    }
#pragma unroll
    for (int i = 0; i < 8; i++) {
        const long long r = brow + ty * 8 + i;
#pragma unroll
        for (int j = 0; j < 4; j++)
            atomicAdd(&C[r * N + tx * 4 + j], acc[i][j]);
    }
}

// ---------------------------------------------------------------------------
// Split-K A^T B with atomic accumulation (C zeroed beforehand).
// ---------------------------------------------------------------------------
__global__ void atb_split_kernel(const float* __restrict__ A,
                                 const float* __restrict__ Bm,
                                 float* __restrict__ C,
                                 int K, int N, int lda, int ldb, int ldc,
                                 long long sA, long long sB, long long sC,
                                 float scale, int ksplit)
{
    const int bz = blockIdx.y;
    A  += (long long)bz * sA;
    Bm += (long long)bz * sB;
    C  += (long long)bz * sC;
    const int bcol = blockIdx.x * 64;
    const int kchunk = K / ksplit;
    const int kbeg = blockIdx.z * kchunk;
    const int kend = kbeg + kchunk;

    __shared__ float As[16][64];
    __shared__ float Bs[16][64];

    const int t  = threadIdx.x;
    const int kk = t >> 4;
    const int c4 = (t & 15) << 2;
    const int ty = t >> 4;
    const int tx = t & 15;

    float acc[4][4];
#pragma unroll
    for (int i = 0; i < 4; i++)
#pragma unroll
        for (int j = 0; j < 4; j++) acc[i][j] = 0.f;

    for (int k0 = kbeg; k0 < kend; k0 += 16) {
        *reinterpret_cast<float4*>(&As[kk][c4]) =
            *reinterpret_cast<const float4*>(&A[(long long)(k0 + kk) * lda + c4]);
        *reinterpret_cast<float4*>(&Bs[kk][c4]) =
            *reinterpret_cast<const float4*>(&Bm[(long long)(k0 + kk) * ldb + bcol + c4]);
        __syncthreads();
#pragma unroll
        for (int k = 0; k < 16; k++) {
            float ar[4], br[4];
            *reinterpret_cast<float4*>(ar) = *reinterpret_cast<const float4*>(&As[k][ty * 4]);
            *reinterpret_cast<float4*>(br) = *reinterpret_cast<const float4*>(&Bs[k][tx * 4]);
#pragma unroll
            for (int i = 0; i < 4; i++)
#pragma unroll
                for (int j = 0; j < 4; j++)
                    acc[i][j] += ar[i] * br[j];
        }
        __syncthreads();
    }
#pragma unroll
    for (int i = 0; i < 4; i++)
#pragma unroll
        for (int j = 0; j < 4; j++)
            atomicAdd(&C[(long long)(ty * 4 + i) * ldc + bcol + tx * 4 + j],
                      acc[i][j] * scale);
}

// ---------------------------------------------------------------------------
// FUSED k/v-LN + dots: per (b,h), dots = LN(k)^T LN(v) / SEQ, split-K atomic.
// Reads k,v rows directly from qkv; inline LN over DH=64 per row via 16-lane
// shfl reduction (the 16 loader threads of a row are lane-aligned).
// grid (1, Bq*NHEAD, ksplit), 256 threads. dots zeroed beforehand.
// ---------------------------------------------------------------------------
__global__ void kvln_dots_kernel(const float* __restrict__ qkv,
                                 const float* __restrict__ kg,
                                 const float* __restrict__ kb,
                                 const float* __restrict__ vg,
                                 const float* __restrict__ vb,
                                 float* __restrict__ C, int ksplit)
{
    const int bh = blockIdx.y;
    const int b  = bh >> 4;
    const int h  = bh & 15;
    float* Cd = C + (long long)bh * DH * DH;
    const int kchunk = SEQ / ksplit;
    const int kbeg = blockIdx.z * kchunk;
    const int kend = kbeg + kchunk;

    __shared__ float As[16][64];   // LN(k) rows
    __shared__ float Bs[16][64];   // LN(v) rows

    const int t  = threadIdx.x;
    const int kk = t >> 4;          // row in 16-row chunk
    const int c4 = (t & 15) << 2;   // col 0..60
    const int ty = t >> 4;
    const int tx = t & 15;

    const float4 kgv = *reinterpret_cast<const float4*>(kg + c4);
    const float4 kbv = *reinterpret_cast<const float4*>(kb + c4);
    const float4 vgv = *reinterpret_cast<const float4*>(vg + c4);
    const float4 vbv = *reinterpret_cast<const float4*>(vb + c4);

    float acc[4][4];
#pragma unroll
    for (int i = 0; i < 4; i++)
#pragma unroll
        for (int j = 0; j < 4; j++) acc[i][j] = 0.f;

    for (int k0 = kbeg; k0 < kend; k0 += 16) {
        const int n = k0 + kk;
        const float* base = qkv +
            ((long long)(b * SEQ + n)) * (3 * HID) + h * DH + c4;
        const float4 kv = *reinterpret_cast<const float4*>(base + HID);
        const float4 vv = *reinterpret_cast<const float4*>(base + 2 * HID);
        float s1 = kv.x + kv.y + kv.z + kv.w;
        float q1 = kv.x * kv.x + kv.y * kv.y + kv.z * kv.z + kv.w * kv.w;
        float s2 = vv.x + vv.y + vv.z + vv.w;
        float q2 = vv.x * vv.x + vv.y * vv.y + vv.z * vv.z + vv.w * vv.w;
#pragma unroll
        for (int o = 8; o; o >>= 1) {
            s1 += __shfl_xor_sync(0xffffffffu, s1, o);
            q1 += __shfl_xor_sync(0xffffffffu, q1, o);
            s2 += __shfl_xor_sync(0xffffffffu, s2, o);
            q2 += __shfl_xor_sync(0xffffffffu, q2, o);
        }
        const float m1 = s1 * (1.f / DH);
        const float r1 = rsqrtf(q1 * (1.f / DH) - m1 * m1 + EPSV);
        const float m2 = s2 * (1.f / DH);
        const float r2 = rsqrtf(q2 * (1.f / DH) - m2 * m2 + EPSV);
        float4 ko, vo;
        ko.x = (kv.x - m1) * r1 * kgv.x + kbv.x;
        ko.y = (kv.y - m1) * r1 * kgv.y + kbv.y;
        ko.z = (kv.z - m1) * r1 * kgv.z + kbv.z;
        ko.w = (kv.w - m1) * r1 * kgv.w + kbv.w;
        vo.x = (vv.x - m2) * r2 * vgv.x + vbv.x;
        vo.y = (vv.y - m2) * r2 * vgv.y + vbv.y;
        vo.z = (vv.z - m2) * r2 * vgv.z + vbv.z;
        vo.w = (vv.w - m2) * r2 * vgv.w + vbv.w;
        *reinterpret_cast<float4*>(&As[kk][c4]) = ko;
        *reinterpret_cast<float4*>(&Bs[kk][c4]) = vo;
        __syncthreads();
#pragma unroll
        for (int k = 0; k < 16; k++) {
            float ar[4], br[4];
            *reinterpret_cast<float4*>(ar) = *reinterpret_cast<const float4*>(&As[k][ty * 4]);
            *reinterpret_cast<float4*>(br) = *reinterpret_cast<const float4*>(&Bs[k][tx * 4]);
#pragma unroll
            for (int i = 0; i < 4; i++)
#pragma unroll
                for (int j = 0; j < 4; j++)
                    acc[i][j] += ar[i] * br[j];
        }
        __syncthreads();
    }
    const float scale = 1.f / (float)SEQ;
#pragma unroll
    for (int i = 0; i < 4; i++)
#pragma unroll
        for (int j = 0; j < 4; j++)
            atomicAdd(&Cd[(long long)(ty * 4 + i) * DH + tx * 4 + j],
                      acc[i][j] * scale);
}

// ---------------------------------------------------------------------------
// attn apply: per (b,h): attn[n,:] = q[n,:] @ dots[b,h] -> split-fp16 output
// ---------------------------------------------------------------------------
__global__ void attn_kernel(const float* __restrict__ qkv,
                            const float* __restrict__ dots,
                            __half* __restrict__ outh,
                            __half* __restrict__ outl)
{
    const int bh = blockIdx.y;
    const int b  = bh >> 4;
    const int h  = bh & 15;
    const float* q = qkv + (long long)b * SEQ * (3 * HID) + h * DH;
    const float* D = dots + (long long)bh * DH * DH;
    const long long cbase = (long long)b * SEQ * HID + h * DH;
    const int row0 = blockIdx.x * 64;

    __shared__ float As[16][64];
    __shared__ float Bs[16][64];

    const int t   = threadIdx.x;
    const int ty  = t >> 4;
    const int tx  = t & 15;
    const int lm  = t >> 2;
    const int lk4 = (t & 3) << 2;
    const int bk  = t >> 4;
    const int bn4 = (t & 15) << 2;

    float acc[4][4];
#pragma unroll
    for (int i = 0; i < 4; i++)
#pragma unroll
        for (int j = 0; j < 4; j++) acc[i][j] = 0.f;

    for (int k0 = 0; k0 < DH; k0 += 16) {
        float4 av = *reinterpret_cast<const float4*>(
            &q[(long long)(row0 + lm) * (3 * HID) + k0 + lk4]);
        As[lk4 + 0][lm] = av.x;
        As[lk4 + 1][lm] = av.y;
        As[lk4 + 2][lm] = av.z;
        As[lk4 + 3][lm] = av.w;
        *reinterpret_cast<float4*>(&Bs[bk][bn4]) =
            *reinterpret_cast<const float4*>(&D[(k0 + bk) * DH + bn4]);
        __syncthreads();
#pragma unroll
        for (int k = 0; k < 16; k++) {
            float ar[4], br[4];
            *reinterpret_cast<float4*>(ar) = *reinterpret_cast<const float4*>(&As[k][ty * 4]);
            *reinterpret_cast<float4*>(br) = *reinterpret_cast<const float4*>(&Bs[k][tx * 4]);
#pragma unroll
            for (int i = 0; i < 4; i++)
#pragma unroll
                for (int j = 0; j < 4; j++)
                    acc[i][j] += ar[i] * br[j];
        }
        __syncthreads();
    }
#pragma unroll
    for (int i = 0; i < 4; i++)
#pragma unroll
        for (int j = 0; j < 4; j += 2) {
            const long long idx = cbase +
                (long long)(row0 + ty * 4 + i) * HID + tx * 4 + j;
            __half h0, l0, h1, l1;
            h_split(acc[i][j],     h0, l0);
            h_split(acc[i][j + 1], h1, l1);
            *reinterpret_cast<__half2*>(outh + idx) = __halves2half2(h0, h1);
            *reinterpret_cast<__half2*>(outl + idx) = __halves2half2(l0, l1);
        }
}

// ---------------------------------------------------------------------------
// Row LayerNorm over H=1024 with split-fp16 output
// ---------------------------------------------------------------------------
__global__ void ln_split_kernel(const float* __restrict__ x,
                                const float* __restrict__ g,
                                const float* __restrict__ b,
                                __half* __restrict__ yh,
                                __half* __restrict__ yl)
{
    const int row = blockIdx.x;
    const float4 v = reinterpret_cast<const float4*>(x + (long long)row * HID)[threadIdx.x];
    float s  = v.x + v.y + v.z + v.w;
    float sq = v.x * v.x + v.y * v.y + v.z * v.z + v.w * v.w;
#pragma unroll
    for (int o = 16; o; o >>= 1) {
        s  += __shfl_xor_sync(0xffffffffu, s,  o);
        sq += __shfl_xor_sync(0xffffffffu, sq, o);
    }
    __shared__ float ss[8], ssq[8];
    const int w = threadIdx.x >> 5, l = threadIdx.x & 31;
    if (l == 0) { ss[w] = s; ssq[w] = sq; }
    __syncthreads();
    if (w == 0) {
        s  = (l < 8) ? ss[l]  : 0.f;
        sq = (l < 8) ? ssq[l] : 0.f;
#pragma unroll
        for (int o = 4; o; o >>= 1) {
            s  += __shfl_xor_sync(0xffffffffu, s,  o);
            sq += __shfl_xor_sync(0xffffffffu, sq, o);
        }
        if (l == 0) { ss[0] = s; ssq[0] = sq; }
    }
    __syncthreads();
    const float mean = ss[0] * (1.f / HID);
    const float var  = ssq[0] * (1.f / HID) - mean * mean;
    const float rstd = rsqrtf(var + EPSV);
    const float4 gg = reinterpret_cast<const float4*>(g)[threadIdx.x];
    const float4 bb = reinterpret_cast<const float4*>(b)[threadIdx.x];
    float o0 = (v.x - mean) * rstd * gg.x + bb.x;
    float o1 = (v.y - mean) * rstd * gg.y + bb.y;
    float o2 = (v.z - mean) * rstd * gg.z + bb.z;
    float o3 = (v.w - mean) * rstd * gg.w + bb.w;
    __half h0, l0, h1, l1, h2, l2, h3, l3;
    h_split(o0, h0, l0); h_split(o1, h1, l1);
    h_split(o2, h2, l2); h_split(o3, h3, l3);
    const long long base = (long long)row * HID + threadIdx.x * 4;
    *reinterpret_cast<__half2*>(yh + base)     = __halves2half2(h0, h1);
    *reinterpret_cast<__half2*>(yh + base + 2) = __halves2half2(h2, h3);
    *reinterpret_cast<__half2*>(yl + base)     = __halves2half2(l0, l1);
    *reinterpret_cast<__half2*>(yl + base + 2) = __halves2half2(l2, l3);
}

// ---------------------------------------------------------------------------
// BatchNorm1d (training stats): two-stage (atomic partials, finalize)
// ---------------------------------------------------------------------------
__global__ void bn_stats1_kernel(const float* __restrict__ xp, float* __restrict__ psum)
{
    const int p = blockIdx.x;
    const int seg = blockIdx.y;
    const int r0 = seg * (MROWS / 8);
    float s = 0.f, sq = 0.f;
    for (int r = r0 + threadIdx.x; r < r0 + MROWS / 8; r += 256) {
        const float v = xp[(long long)r * PSI + p];
        s += v; sq += v * v;
    }
#pragma unroll
    for (int o = 16; o; o >>= 1) {
        s  += __shfl_xor_sync(0xffffffffu, s,  o);
        sq += __shfl_xor_sync(0xffffffffu, sq, o);
    }
    __shared__ float ss[8], ssq[8];
    const int w = threadIdx.x >> 5, l = threadIdx.x & 31;
    if (l == 0) { ss[w] = s; ssq[w] = sq; }
    __syncthreads();
    if (threadIdx.x == 0) {
        float ts = 0.f, tq = 0.f;
        for (int i = 0; i < 8; i++) { ts += ss[i]; tq += ssq[i]; }
        atomicAdd(&psum[p], ts);
        atomicAdd(&psum[PSI + p], tq);
    }
}

__global__ void bn_stats2_kernel(const float* __restrict__ psum, float* __restrict__ stats)
{
    const int p = threadIdx.x;
    const float mean = psum[p] * (1.f / MROWS);
    const float var  = psum[PSI + p] * (1.f / MROWS) - mean * mean;
    stats[p]       = mean;
    stats[PSI + p] = rsqrtf(var + EPSV);
}

__global__ void bn_apply_kernel(const float* __restrict__ xp,
                                const float* __restrict__ stats,
                                const float* __restrict__ bng,
                                const float* __restrict__ bnb,
                                const float* __restrict__ mu,
                                float* __restrict__ xn,
                                float* __restrict__ xs)
{
    const long long i = (long long)blockIdx.x * 256 + threadIdx.x;
    const int p = (int)(i & (PSI - 1));
    const float v = (xp[i] - stats[p]) * stats[PSI + p] * bng[p] + bnb[p];
    xn[i] = v;
    const float m = mu[p];
    const float sp = (m > 20.f) ? m : log1pf(expf(m));
    xs[i] = v * sp;
}

// ---------------------------------------------------------------------------
// Launch
// ---------------------------------------------------------------------------
extern "C" void kernel_launch(void* const* d_in, const int* in_sizes, int n_in,
                              void* d_out, int out_size)
{
    const float* x    = (const float*)d_in[0];
    const float* fx   = (const float*)d_in[1];
    const float* mu   = (const float*)d_in[2];
    const float* ln1g = (const float*)d_in[3];
    const float* ln1b = (const float*)d_in[4];
    const float* Wqkv = (const float*)d_in[5];
    const float* kg   = (const float*)d_in[6];
    const float* kb   = (const float*)d_in[7];
    const float* vg   = (const float*)d_in[8];
    const float* vb   = (const float*)d_in[9];
    const float* Wout = (const float*)d_in[10];
    const float* bout = (const float*)d_in[11];
    const float* ln2g = (const float*)d_in[12];
    const float* ln2b = (const float*)d_in[13];
    const float* W1   = (const float*)d_in[14];
    const float* b1   = (const float*)d_in[15];
    const float* W2   = (const float*)d_in[16];
    const float* b2   = (const float*)d_in[17];
    const float* Wp   = (const float*)d_in[18];
    const float* bp   = (const float*)d_in[19];  // BN-invariant; unused
    const float* bng  = (const float*)d_in[20];
    const float* bnb  = (const float*)d_in[21];
    const float* ln3g = (const float*)d_in[22];
    const float* ln3b = (const float*)d_in[23];
    const float* W3   = (const float*)d_in[24];
    const float* b3   = (const float*)d_in[25];
    const float* W4   = (const float*)d_in[26];
    const float* b4   = (const float*)d_in[27];
    (void)bp;

    float* outx  = (float*)d_out;
    float* outfx = outx + (long long)MROWS * HID;

    float *p_qkv, *p_dots, *p_x1;
    float *p_xp, *p_xn, *p_xs, *p_stats, *p_psum, *p_kern, *p_fx1;
    __half *p_wh, *p_wl, *p_lnh, *p_lnl, *p_atth, *p_attl, *p_midh, *p_midl;
    cudaGetSymbolAddress((void**)&p_qkv,  g_qkv);
    cudaGetSymbolAddress((void**)&p_dots, g_dots);
    cudaGetSymbolAddress((void**)&p_x1,   g_x1);
    cudaGetSymbolAddress((void**)&p_xp,   g_xp);
    cudaGetSymbolAddress((void**)&p_xn,   g_xn);
    cudaGetSymbolAddress((void**)&p_xs,   g_xs);
    cudaGetSymbolAddress((void**)&p_stats,g_stats);
    cudaGetSymbolAddress((void**)&p_psum, g_psum);
    cudaGetSymbolAddress((void**)&p_kern, g_kern);
    cudaGetSymbolAddress((void**)&p_fx1,  g_fx1);
    cudaGetSymbolAddress((void**)&p_wh,   g_wh);
    cudaGetSymbolAddress((void**)&p_wl,   g_wl);
    cudaGetSymbolAddress((void**)&p_lnh,  g_lnh);
    cudaGetSymbolAddress((void**)&p_lnl,  g_lnl);
    cudaGetSymbolAddress((void**)&p_atth, g_atth);
    cudaGetSymbolAddress((void**)&p_attl, g_attl);
    cudaGetSymbolAddress((void**)&p_midh, g_midh);
    cudaGetSymbolAddress((void**)&p_midl, g_midl);

    cudaFuncSetAttribute(h16_gemm_kernel<false, false, false, false>,
                         cudaFuncAttributeMaxDynamicSharedMemorySize, H16_SMEM_BYTES);
    cudaFuncSetAttribute(h16_gemm_kernel<true, true, false, false>,
                         cudaFuncAttributeMaxDynamicSharedMemorySize, H16_SMEM_BYTES);
    cudaFuncSetAttribute(h16_gemm_kernel<true, false, true, true>,
                         cudaFuncAttributeMaxDynamicSharedMemorySize, H16_SMEM_BYTES);
    cudaFuncSetAttribute(h16_gemm_kernel<true, false, false, false>,
                         cudaFuncAttributeMaxDynamicSharedMemorySize, H16_SMEM_BYTES);

    // 0) pre-split all weights to fp16 pairs (single batched launch)
    wsplit_all_kernel<<<WTOT / 1024, 256>>>(Wqkv, Wout, W1, W2, W3, W4, p_wh, p_wl);

    // 1) h = LN1(x) -> split
    ln_split_kernel<<<MROWS, 256>>>(x, ln1g, ln1b, p_lnh, p_lnl);
    // 2) qkv = h @ Wqkv
    h16_gemm_kernel<false, false, false, false><<<dim3(24, 128), 256, H16_SMEM_BYTES>>>(
        p_lnh, p_lnl, p_wh + OFF_QKV, p_wl + OFF_QKV,
        p_qkv, nullptr, nullptr, nullptr, nullptr, MROWS, HID, 3 * HID);
    // 3+4) dots = LN(k)^T LN(v) / SEQ (fused LN + split-K, atomic)
    cudaMemsetAsync(p_dots, 0, sizeof(float) * Bq * NHEAD * DH * DH);
    kvln_dots_kernel<<<dim3(1, Bq * NHEAD, 16), 256>>>(
        p_qkv, kg, kb, vg, vb, p_dots, 16);
    // 5) attn = q @ dots -> split
    attn_kernel<<<dim3(SEQ / 64, Bq * NHEAD), 256>>>(p_qkv, p_dots, p_atth, p_attl);
    // 6) x1 = attn @ Wout + bout + x
    h16_gemm_kernel<true, true, false, false><<<dim3(8, 128), 256, H16_SMEM_BYTES>>>(
        p_atth, p_attl, p_wh + OFF_WOUT, p_wl + OFF_WOUT,
        p_x1, nullptr, nullptr, bout, x, MROWS, HID, HID);
    // 7) h = LN2(x1) -> split
    ln_split_kernel<<<MROWS, 256>>>(p_x1, ln2g, ln2b, p_lnh, p_lnl);
    // 8) mid = gelu(h @ W1 + b1) -> split
    h16_gemm_kernel<true, false, true, true><<<dim3(32, 128), 256, H16_SMEM_BYTES>>>(
        p_lnh, p_lnl, p_wh + OFF_W1, p_wl + OFF_W1,
        nullptr, p_midh, p_midl, b1, nullptr, MROWS, HID, 4 * HID);
    // 9) x_out = mid @ W2 + b2 + x1 -> d_out first half
    h16_gemm_kernel<true, true, false, false><<<dim3(8, 128), 256, H16_SMEM_BYTES>>>(
        p_midh, p_midl, p_wh + OFF_W2, p_wl + OFF_W2,
        outx, nullptr, nullptr, b2, p_x1, MROWS, 4 * HID, HID);
    // 10) xp = x_out @ Wp (bias bp cancels in BN) -- split-K x8, atomics
    cudaMemsetAsync(p_xp, 0, sizeof(float) * MROWS * PSI);
    sgemm_nk_splitk_kernel<<<dim3(1, MROWS / 128, 8), 256>>>(
        outx, Wp, p_xp, MROWS, HID, PSI, 8);
    // 11-12) BatchNorm (two-stage stats) + softplus scaling
    cudaMemsetAsync(p_psum, 0, sizeof(float) * 2 * PSI);
    bn_stats1_kernel<<<dim3(PSI, 8), 256>>>(p_xp, p_psum);
    bn_stats2_kernel<<<1, PSI>>>(p_psum, p_stats);
    bn_apply_kernel<<<(MROWS * PSI) / 256, 256>>>(p_xp, p_stats, bng, bnb, mu, p_xn, p_xs);
    // 13) kern = x_^T @ fx per batch
    cudaMemsetAsync(p_kern, 0, sizeof(float) * Bq * PSI * HID);
    atb_split_kernel<<<dim3(HID / 64, Bq, 16), 256>>>(
        p_xn, fx, p_kern, SEQ, HID, PSI, HID, HID,
        (long long)SEQ * PSI, (long long)SEQ * HID, (long long)PSI * HID, 1.f, 16);
    // 14) fx1 = (x_ * sp(mu)) @ kern + fx per batch (fp32, K=64)
    sgemm_kernel<false, true, false><<<dim3(8, 32, Bq), 256>>>(
        p_xs, p_kern, p_fx1, nullptr, fx, SEQ, PSI, HID,
        (long long)SEQ * PSI, (long long)PSI * HID,
        (long long)SEQ * HID, (long long)SEQ * HID);
    // 15) h = LN3(fx1) -> split
    ln_split_kernel<<<MROWS, 256>>>(p_fx1, ln3g, ln3b, p_lnh, p_lnl);
    // 16) mid = gelu(h @ W3 + b3) -> split
    h16_gemm_kernel<true, false, true, true><<<dim3(32, 128), 256, H16_SMEM_BYTES>>>(
        p_lnh, p_lnl, p_wh + OFF_W3, p_wl + OFF_W3,
        nullptr, p_midh, p_midl, b3, nullptr, MROWS, HID, 4 * HID);
    // 17) fx_out = mid @ W4 + b4 -> d_out second half
    h16_gemm_kernel<true, false, false, false><<<dim3(8, 128), 256, H16_SMEM_BYTES>>>(
        p_midh, p_midl, p_wh + OFF_W4, p_wl + OFF_W4,
        outfx, nullptr, nullptr, b4, nullptr, MROWS, 4 * HID, HID);
}